// round 9
// baseline (speedup 1.0000x reference)
#include <cuda_runtime.h>
#include <cstdint>

#define N_NODES 100000
#define N_EDGES 1600000
#define IN_C 128
#define HID_C 256
#define OUT_C 128
#define SCAN_NB ((N_NODES + 1023) / 1024)   // 98

// ================= scratch =================
__device__ float4 g_h [N_NODES * HID_C / 4];     // conv1 output (relu)
__device__ float  g_Wf1[IN_C * HID_C];           // fragment-packed weights
__device__ float  g_Wf2[HID_C * HID_C];
__device__ float  g_Wf3[HID_C * HID_C];
__device__ float  g_Wf4[HID_C * OUT_C];
__device__ int    g_cnt[N_NODES];
__device__ int    g_rowoff[N_NODES + 1];
__device__ int    g_cursor[N_NODES];
__device__ int    g_csrsrc[N_EDGES];
__device__ int    g_bsum[SCAN_NB];

// ================= helpers =================
__device__ __forceinline__ uint32_t smem_u32(const void* p) {
    uint32_t a;
    asm("{ .reg .u64 t; cvta.to.shared.u64 t, %1; cvt.u32.u64 %0, t; }" : "=r"(a) : "l"(p));
    return a;
}
__device__ __forceinline__ float round_tf32(float x) {
    float r;
    asm("cvt.rna.tf32.f32 %0, %1;" : "=f"(r) : "f"(x));
    return r;
}
__device__ __forceinline__ void cp_async16(uint32_t dst, const void* src, bool pred) {
    int sz = pred ? 16 : 0;
    asm volatile("cp.async.ca.shared.global [%0], [%1], 16, %2;"
                 :: "r"(dst), "l"(src), "r"(sz) : "memory");
}
#define CP_COMMIT() asm volatile("cp.async.commit_group;" ::: "memory")
#define CP_WAIT(n)  asm volatile("cp.async.wait_group %0;" :: "n"(n) : "memory")

__device__ __forceinline__ void mma_tf32(float* d, uint32_t a0, uint32_t a1,
                                         uint32_t a2, uint32_t a3,
                                         uint32_t b0, uint32_t b1) {
    asm volatile(
        "mma.sync.aligned.m16n8k8.row.col.f32.tf32.tf32.f32 "
        "{%0,%1,%2,%3}, {%4,%5,%6,%7}, {%8,%9}, {%0,%1,%2,%3};"
        : "+f"(d[0]), "+f"(d[1]), "+f"(d[2]), "+f"(d[3])
        : "r"(a0), "r"(a1), "r"(a2), "r"(a3), "r"(b0), "r"(b1));
}
__device__ __forceinline__ float4 f4add(float4 a, float4 b) {
    return make_float4(a.x + b.x, a.y + b.y, a.z + b.z, a.w + b.w);
}

// ================= weight fragment-pack =================
// Per 32-k group g: [ks(4)][wt(NT)][p(4)][lane(32)] float4
// q = {W[k0][n0], W[k0+4][n0], W[k0][n0+8], W[k0+4][n0+8]},
// n0 = wt*64 + 2p*8 + lane/4, k0 = g*32 + ks*8 + lane%4
template <int K, int NTOT>
__global__ void pack_kernel(const float* __restrict__ W, float* __restrict__ Wf)
{
    constexpr int NT = NTOT / 64;
    constexpr int PER_G = 512 * NT;
    int id = blockIdx.x * 256 + threadIdx.x;
    if (id >= K * NTOT / 4) return;
    int q  = id % PER_G;
    int g  = id / PER_G;
    int lane = q & 31;
    int p    = (q >> 5) & 3;
    int wt   = (q >> 7) % NT;
    int ks   = (q >> 7) / NT;

    int n0 = wt * 64 + 2 * p * 8 + (lane >> 2);
    int k0 = g * 32 + ks * 8 + (lane & 3);
    float4 v;
    v.x = round_tf32(W[(size_t)k0       * NTOT + n0]);
    v.y = round_tf32(W[(size_t)(k0 + 4) * NTOT + n0]);
    v.z = round_tf32(W[(size_t)k0       * NTOT + n0 + 8]);
    v.w = round_tf32(W[(size_t)(k0 + 4) * NTOT + n0 + 8]);
    ((float4*)Wf)[id] = v;
}

// ================= CSR build =================
__global__ void hist_kernel(const int* __restrict__ dst, int* __restrict__ cnt)
{
    int e = blockIdx.x * 256 + threadIdx.x;
    if (e < N_EDGES) atomicAdd(&cnt[dst[e]], 1);
}

__global__ void scan1_kernel(const int* __restrict__ cnt, int* __restrict__ rowoff,
                             int* __restrict__ bsum)
{
    __shared__ int sh[1024];
    int tid = threadIdx.x;
    int i = blockIdx.x * 1024 + tid;
    int v = (i < N_NODES) ? cnt[i] : 0;
    sh[tid] = v;
    __syncthreads();
#pragma unroll
    for (int off = 1; off < 1024; off <<= 1) {
        int t = (tid >= off) ? sh[tid - off] : 0;
        __syncthreads();
        sh[tid] += t;
        __syncthreads();
    }
    if (i < N_NODES) rowoff[i] = sh[tid] - v;
    if (tid == 1023) bsum[blockIdx.x] = sh[tid];
}

__global__ void scan2_kernel(int* __restrict__ bsum)
{
    __shared__ int sh[128];
    int tid = threadIdx.x;
    int v = (tid < SCAN_NB) ? bsum[tid] : 0;
    sh[tid] = v;
    __syncthreads();
#pragma unroll
    for (int off = 1; off < 128; off <<= 1) {
        int t = (tid >= off) ? sh[tid - off] : 0;
        __syncthreads();
        sh[tid] += t;
        __syncthreads();
    }
    if (tid < SCAN_NB) bsum[tid] = sh[tid] - v;
}

__global__ void scan3_kernel(int* __restrict__ rowoff, const int* __restrict__ bsum,
                             int* __restrict__ cursor)
{
    int i = blockIdx.x * 1024 + threadIdx.x;
    if (i < N_NODES) {
        int r = rowoff[i] + bsum[blockIdx.x];
        rowoff[i] = r;
        cursor[i] = r;
    }
    if (i == 0) rowoff[N_NODES] = N_EDGES;
}

__global__ void fill_kernel(const int* __restrict__ src, const int* __restrict__ dst,
                            int* __restrict__ cursor, int* __restrict__ csrsrc)
{
    int e = blockIdx.x * 256 + threadIdx.x;
    if (e >= N_EDGES) return;
    int pos = atomicAdd(&cursor[dst[e]], 1);
    csrsrc[pos] = src[e];
}

// ================= fused conv: gather + 2-layer MLP, BM=64, 2 CTAs/SM =================
// C[M,N2] = act( relu( (X + gathersum(X)) @ W1 + b1 ) @ W2 + b2 )
// 256 threads = 8 warps: wm = wid&1 (2x32 rows), wn = wid>>1 (4 col groups)
template <int K, int N2, bool OUTER_RELU>
__global__ void __launch_bounds__(256, 2) fused_conv(
    const float4* __restrict__ X,       // [N_NODES, K/4]
    const int* __restrict__ rowoff,
    const int* __restrict__ csrsrc,
    const float* __restrict__ Wp1,      // packed [K x 256]
    const float* __restrict__ b1v,
    const float* __restrict__ Wp2,      // packed [256 x N2]
    const float* __restrict__ b2v,
    float* __restrict__ C)
{
    constexpr int BM = 64;
    constexpr int GA = K / 32, GB = HID_C / 32;
    constexpr int V  = K / 4;                 // float4 per input row
    constexpr int J  = V / 32;                // float4 per lane (1 or 2)
    constexpr int HPITCH = 260;
    constexpr int AH = BM * HPITCH;           // 16640 floats: A tile, later H tile
    constexpr int W1F4 = 2048;                // float4 per W1 chunk (32k x 256n)
    constexpr int W2F4 = 512 * (N2 / 64);     // float4 per W2 chunk
    constexpr int NF  = N2 / 32;              // phase-4 frags per warp (8 or 4)
    constexpr int NPL = NF / 2;
    constexpr int NT2 = N2 / 64;
    constexpr int M = N_NODES;

    extern __shared__ float sm[];             // [AH + 8192]
    const uint32_t sbase = smem_u32(sm);
    const uint32_t wbase = sbase + AH * 4u;

    const int tid  = threadIdx.x;
    const int wid  = tid >> 5;
    const int lane = tid & 31;
    const int gid  = lane >> 2;
    const int tig  = lane & 3;
    const int wm   = wid & 1;
    const int wn   = wid >> 1;                // 0..3
    const int rA   = wm * 32;
    const int m0   = blockIdx.x * BM;

    // ---- W chunk loader (single buffer) ----
    auto loadW1 = [&](int g) {
#pragma unroll
        for (int j = 0; j < W1F4 / 256; j++) {
            int idx = j * 256 + tid;
            cp_async16(wbase + (uint32_t)idx * 16u,
                       Wp1 + ((size_t)g * W1F4 + idx) * 4, true);
        }
        CP_COMMIT();
    };
    auto loadW2 = [&](int g) {
#pragma unroll
        for (int j = 0; j < W2F4 / 256; j++) {
            int idx = j * 256 + tid;
            cp_async16(wbase + (uint32_t)idx * 16u,
                       Wp2 + ((size_t)g * W2F4 + idx) * 4, true);
        }
        CP_COMMIT();
    };

    loadW1(0);   // overlaps with gather below

    // ---- phase 0: gather agg rows into smem A tile ----
    {
#pragma unroll 1
        for (int i = 0; i < 8; i++) {
            int r = wid * 8 + i;
            int node = m0 + r;
            float4 acc[J];
            if (node < M) {
#pragma unroll
                for (int j = 0; j < J; j++)
                    acc[j] = X[(size_t)node * V + j * 32 + lane];
                int b = __ldg(&rowoff[node]);
                int e = __ldg(&rowoff[node + 1]);
                for (; b + 1 < e; b += 2) {
                    int s0 = __ldg(&csrsrc[b]);
                    int s1 = __ldg(&csrsrc[b + 1]);
#pragma unroll
                    for (int j = 0; j < J; j++) {
                        float4 v0 = X[(size_t)s0 * V + j * 32 + lane];
                        float4 v1 = X[(size_t)s1 * V + j * 32 + lane];
                        acc[j] = f4add(acc[j], f4add(v0, v1));
                    }
                }
                if (b < e) {
                    int s0 = __ldg(&csrsrc[b]);
#pragma unroll
                    for (int j = 0; j < J; j++)
                        acc[j] = f4add(acc[j], X[(size_t)s0 * V + j * 32 + lane]);
                }
            } else {
#pragma unroll
                for (int j = 0; j < J; j++)
                    acc[j] = make_float4(0.f, 0.f, 0.f, 0.f);
            }
#pragma unroll
            for (int j = 0; j < J; j++)
                *(float4*)&sm[(size_t)r * HPITCH + (j * 32 + lane) * 4] = acc[j];
        }
    }
    CP_WAIT(0);
    __syncthreads();   // A tile + W1 chunk 0 ready

    float acc[2][8][4];
#pragma unroll
    for (int i = 0; i < 2; i++)
#pragma unroll
        for (int j = 0; j < 8; j++)
#pragma unroll
            for (int c = 0; c < 4; c++) acc[i][j][c] = 0.0f;

    // ---- phase A: Hacc = A @ W1 (A from smem, W1 streamed) ----
    for (int g = 0; g < GA; g++) {
        const float* bs = sm + AH;
#pragma unroll
        for (int ks = 0; ks < 4; ks++) {
            const int k0 = g * 32 + ks * 8;
            uint32_t a[2][4];
#pragma unroll
            for (int mf = 0; mf < 2; mf++) {
                int base = rA + mf * 16;
                a[mf][0] = __float_as_uint(round_tf32(sm[(size_t)(base + gid)     * HPITCH + k0 + tig]));
                a[mf][1] = __float_as_uint(round_tf32(sm[(size_t)(base + gid + 8) * HPITCH + k0 + tig]));
                a[mf][2] = __float_as_uint(round_tf32(sm[(size_t)(base + gid)     * HPITCH + k0 + tig + 4]));
                a[mf][3] = __float_as_uint(round_tf32(sm[(size_t)(base + gid + 8) * HPITCH + k0 + tig + 4]));
            }
            uint32_t b[8][2];
#pragma unroll
            for (int p = 0; p < 4; p++) {
                float4 q = *(const float4*)&bs[(((ks * 4 + wn) * 4 + p) * 32 + lane) * 4];
                b[2 * p][0]     = __float_as_uint(q.x);
                b[2 * p][1]     = __float_as_uint(q.y);
                b[2 * p + 1][0] = __float_as_uint(q.z);
                b[2 * p + 1][1] = __float_as_uint(q.w);
            }
#pragma unroll
            for (int mf = 0; mf < 2; mf++)
#pragma unroll
                for (int nf = 0; nf < 8; nf++)
                    mma_tf32(acc[mf][nf], a[mf][0], a[mf][1], a[mf][2], a[mf][3],
                             b[nf][0], b[nf][1]);
        }
        __syncthreads();                       // all warps done with W chunk
        if (g + 1 < GA) {
            loadW1(g + 1);
            CP_WAIT(0);
            __syncthreads();
        }
    }

    // prefetch W2 chunk 0; overlaps with H spill
    loadW2(0);

    // ---- phase 3: H = round_tf32(relu(acc + b1)) into smem (overlays A) ----
#pragma unroll
    for (int nf = 0; nf < 8; nf++) {
        int col = wn * 64 + nf * 8 + tig * 2;
        float c0 = b1v[col], c1 = b1v[col + 1];
#pragma unroll
        for (int mf = 0; mf < 2; mf++) {
            int r0 = rA + mf * 16 + gid;
            sm[(size_t)r0 * HPITCH + col]           = round_tf32(fmaxf(acc[mf][nf][0] + c0, 0.f));
            sm[(size_t)r0 * HPITCH + col + 1]       = round_tf32(fmaxf(acc[mf][nf][1] + c1, 0.f));
            sm[(size_t)(r0 + 8) * HPITCH + col]     = round_tf32(fmaxf(acc[mf][nf][2] + c0, 0.f));
            sm[(size_t)(r0 + 8) * HPITCH + col + 1] = round_tf32(fmaxf(acc[mf][nf][3] + c1, 0.f));
        }
    }
#pragma unroll
    for (int i = 0; i < 2; i++)
#pragma unroll
        for (int j = 0; j < 8; j++)
#pragma unroll
            for (int c = 0; c < 4; c++) acc[i][j][c] = 0.0f;

    CP_WAIT(0);
    __syncthreads();   // H tile + W2 chunk 0 ready

    // ---- phase 4: OUT = H @ W2 ----
    const int grp = (NF == 8) ? wn : (wn >> 1);
    for (int g = 0; g < GB; g++) {
        const float* bs = sm + AH;
#pragma unroll
        for (int ks = 0; ks < 4; ks++) {
            const int k0 = g * 32 + ks * 8;
            uint32_t a[2][4];
#pragma unroll
            for (int mf = 0; mf < 2; mf++) {
                int base = rA + mf * 16;
                a[mf][0] = __float_as_uint(sm[(size_t)(base + gid)     * HPITCH + k0 + tig]);
                a[mf][1] = __float_as_uint(sm[(size_t)(base + gid + 8) * HPITCH + k0 + tig]);
                a[mf][2] = __float_as_uint(sm[(size_t)(base + gid)     * HPITCH + k0 + tig + 4]);
                a[mf][3] = __float_as_uint(sm[(size_t)(base + gid + 8) * HPITCH + k0 + tig + 4]);
            }
            uint32_t b[8][2];
#pragma unroll
            for (int pl = 0; pl < NPL; pl++) {
                int p = (NF == 8) ? pl : (2 * (wn & 1) + pl);
                float4 q = *(const float4*)&bs[(((ks * NT2 + grp) * 4 + p) * 32 + lane) * 4];
                b[2 * pl][0]     = __float_as_uint(q.x);
                b[2 * pl][1]     = __float_as_uint(q.y);
                b[2 * pl + 1][0] = __float_as_uint(q.z);
                b[2 * pl + 1][1] = __float_as_uint(q.w);
            }
#pragma unroll
            for (int mf = 0; mf < 2; mf++)
#pragma unroll
                for (int nf = 0; nf < NF; nf++)
                    mma_tf32(acc[mf][nf], a[mf][0], a[mf][1], a[mf][2], a[mf][3],
                             b[nf][0], b[nf][1]);
        }
        __syncthreads();
        if (g + 1 < GB) {
            loadW2(g + 1);
            CP_WAIT(0);
            __syncthreads();
        }
    }

    // ---- epilogue ----
#pragma unroll
    for (int nf = 0; nf < NF; nf++) {
        int col = wn * (N2 / 4) + nf * 8 + tig * 2;
        float c0 = b2v[col], c1 = b2v[col + 1];
#pragma unroll
        for (int mf = 0; mf < 2; mf++) {
            int r0 = m0 + rA + mf * 16 + gid;
            float v0 = acc[mf][nf][0] + c0, v1 = acc[mf][nf][1] + c1;
            float v2 = acc[mf][nf][2] + c0, v3 = acc[mf][nf][3] + c1;
            if (OUTER_RELU) {
                v0 = fmaxf(v0, 0.f); v1 = fmaxf(v1, 0.f);
                v2 = fmaxf(v2, 0.f); v3 = fmaxf(v3, 0.f);
            }
            if (r0 < M)     *(float2*)&C[(size_t)r0 * N2 + col]       = make_float2(v0, v1);
            if (r0 + 8 < M) *(float2*)&C[(size_t)(r0 + 8) * N2 + col] = make_float2(v2, v3);
        }
    }
}

// ================= launch =================
extern "C" void kernel_launch(void* const* d_in, const int* in_sizes, int n_in,
                              void* d_out, int out_size)
{
    const float* x   = (const float*)d_in[0];
    const int*   ei  = (const int*)d_in[1];
    const float* W1a = (const float*)d_in[2];
    const float* b1a = (const float*)d_in[3];
    const float* W2a = (const float*)d_in[4];
    const float* b2a = (const float*)d_in[5];
    const float* W1b = (const float*)d_in[6];
    const float* b1b = (const float*)d_in[7];
    const float* W2b = (const float*)d_in[8];
    const float* b2b = (const float*)d_in[9];
    float* out = (float*)d_out;

    float4 *h;
    float *Wf1, *Wf2, *Wf3, *Wf4;
    int *cnt, *rowoff, *cursor, *csrsrc, *bsum;
    cudaGetSymbolAddress((void**)&h,    g_h);
    cudaGetSymbolAddress((void**)&Wf1,  g_Wf1);
    cudaGetSymbolAddress((void**)&Wf2,  g_Wf2);
    cudaGetSymbolAddress((void**)&Wf3,  g_Wf3);
    cudaGetSymbolAddress((void**)&Wf4,  g_Wf4);
    cudaGetSymbolAddress((void**)&cnt,    g_cnt);
    cudaGetSymbolAddress((void**)&rowoff, g_rowoff);
    cudaGetSymbolAddress((void**)&cursor, g_cursor);
    cudaGetSymbolAddress((void**)&csrsrc, g_csrsrc);
    cudaGetSymbolAddress((void**)&bsum,   g_bsum);

    const int* src = ei;
    const int* dst = ei + N_EDGES;

    const int convTiles = (N_NODES + 63) / 64;   // 1563
    const int eBlocks = (N_EDGES + 255) / 256;

    const int SMEM = (64 * 260 + 8192) * 4;      // 99328 B -> 2 CTAs/SM
    cudaFuncSetAttribute(fused_conv<IN_C,  HID_C, true >,
                         cudaFuncAttributeMaxDynamicSharedMemorySize, SMEM);
    cudaFuncSetAttribute(fused_conv<HID_C, OUT_C, false>,
                         cudaFuncAttributeMaxDynamicSharedMemorySize, SMEM);

    // ---- CSR build (dst-sorted) ----
    cudaMemsetAsync(cnt, 0, N_NODES * sizeof(int));
    hist_kernel<<<eBlocks, 256>>>(dst, cnt);
    scan1_kernel<<<SCAN_NB, 1024>>>(cnt, rowoff, bsum);
    scan2_kernel<<<1, 128>>>(bsum);
    scan3_kernel<<<SCAN_NB, 1024>>>(rowoff, bsum, cursor);
    fill_kernel<<<eBlocks, 256>>>(src, dst, cursor, csrsrc);

    // ---- weight fragment packs ----
    pack_kernel<IN_C,  HID_C><<<(IN_C * HID_C / 4 + 255) / 256, 256>>>(W1a, Wf1);
    pack_kernel<HID_C, HID_C><<<(HID_C * HID_C / 4 + 255) / 256, 256>>>(W2a, Wf2);
    pack_kernel<HID_C, HID_C><<<(HID_C * HID_C / 4 + 255) / 256, 256>>>(W1b, Wf3);
    pack_kernel<HID_C, OUT_C><<<(HID_C * OUT_C / 4 + 255) / 256, 256>>>(W2b, Wf4);

    // ---- conv1: gather + MLP fused ----
    fused_conv<IN_C, HID_C, true><<<convTiles, 256, SMEM>>>(
        (const float4*)x, rowoff, csrsrc, Wf1, b1a, Wf2, b2a, (float*)h);

    // ---- conv2: gather + MLP fused ----
    fused_conv<HID_C, OUT_C, false><<<convTiles, 256, SMEM>>>(
        (const float4*)h, rowoff, csrsrc, Wf3, b1b, Wf4, b2b, out);
}

// round 10
// speedup vs baseline: 1.0541x; 1.0541x over previous
#include <cuda_runtime.h>
#include <cstdint>

#define N_NODES 100000
#define N_EDGES 1600000
#define IN_C 128
#define HID_C 256
#define OUT_C 128
#define SCAN_NB ((N_NODES + 1023) / 1024)   // 98
#define NSLICES 4
#define TILES_TOTAL ((N_NODES + 127) / 128) // 782
#define TPS ((TILES_TOTAL + NSLICES - 1) / NSLICES)  // 196 tiles per slice

// ================= scratch =================
__device__ float4 g_agg1[N_NODES * IN_C / 4];
__device__ float4 g_h   [N_NODES * HID_C / 4];
__device__ float4 g_agg2[N_NODES * HID_C / 4];
__device__ float  g_Wf1[IN_C * HID_C];
__device__ float  g_Wf2[HID_C * HID_C];
__device__ float  g_Wf3[HID_C * HID_C];
__device__ float  g_Wf4[HID_C * OUT_C];
__device__ int    g_cnt[N_NODES];
__device__ int    g_rowoff[N_NODES + 1];
__device__ int    g_cursor[N_NODES];
__device__ int    g_csrsrc[N_EDGES];
__device__ int    g_bsum[SCAN_NB];

// ================= helpers =================
__device__ __forceinline__ uint32_t smem_u32(const void* p) {
    uint32_t a;
    asm("{ .reg .u64 t; cvta.to.shared.u64 t, %1; cvt.u32.u64 %0, t; }" : "=r"(a) : "l"(p));
    return a;
}
__device__ __forceinline__ float round_tf32(float x) {
    float r;
    asm("cvt.rna.tf32.f32 %0, %1;" : "=f"(r) : "f"(x));
    return r;
}
__device__ __forceinline__ void cp_async16(uint32_t dst, const void* src, bool pred) {
    int sz = pred ? 16 : 0;
    asm volatile("cp.async.ca.shared.global [%0], [%1], 16, %2;"
                 :: "r"(dst), "l"(src), "r"(sz) : "memory");
}
#define CP_COMMIT() asm volatile("cp.async.commit_group;" ::: "memory")
#define CP_WAIT(n)  asm volatile("cp.async.wait_group %0;" :: "n"(n) : "memory")

__device__ __forceinline__ void mma_tf32(float* d, uint32_t a0, uint32_t a1,
                                         uint32_t a2, uint32_t a3,
                                         uint32_t b0, uint32_t b1) {
    asm volatile(
        "mma.sync.aligned.m16n8k8.row.col.f32.tf32.tf32.f32 "
        "{%0,%1,%2,%3}, {%4,%5,%6,%7}, {%8,%9}, {%0,%1,%2,%3};"
        : "+f"(d[0]), "+f"(d[1]), "+f"(d[2]), "+f"(d[3])
        : "r"(a0), "r"(a1), "r"(a2), "r"(a3), "r"(b0), "r"(b1));
}
__device__ __forceinline__ float4 f4add(float4 a, float4 b) {
    return make_float4(a.x + b.x, a.y + b.y, a.z + b.z, a.w + b.w);
}

// ================= weight fragment-pack =================
template <int K, int NTOT>
__global__ void pack_kernel(const float* __restrict__ W, float* __restrict__ Wf)
{
    constexpr int NT = NTOT / 64;
    constexpr int PER_G = 512 * NT;
    int id = blockIdx.x * 256 + threadIdx.x;
    if (id >= K * NTOT / 4) return;
    int q  = id % PER_G;
    int g  = id / PER_G;
    int lane = q & 31;
    int p    = (q >> 5) & 3;
    int wt   = (q >> 7) % NT;
    int ks   = (q >> 7) / NT;

    int n0 = wt * 64 + 2 * p * 8 + (lane >> 2);
    int k0 = g * 32 + ks * 8 + (lane & 3);
    float4 v;
    v.x = round_tf32(W[(size_t)k0       * NTOT + n0]);
    v.y = round_tf32(W[(size_t)(k0 + 4) * NTOT + n0]);
    v.z = round_tf32(W[(size_t)k0       * NTOT + n0 + 8]);
    v.w = round_tf32(W[(size_t)(k0 + 4) * NTOT + n0 + 8]);
    ((float4*)Wf)[id] = v;
}

// ================= CSR build =================
__global__ void hist_kernel(const int* __restrict__ dst, int* __restrict__ cnt)
{
    int e = blockIdx.x * 256 + threadIdx.x;
    if (e < N_EDGES) atomicAdd(&cnt[dst[e]], 1);
}

__global__ void scan1_kernel(const int* __restrict__ cnt, int* __restrict__ rowoff,
                             int* __restrict__ bsum)
{
    __shared__ int sh[1024];
    int tid = threadIdx.x;
    int i = blockIdx.x * 1024 + tid;
    int v = (i < N_NODES) ? cnt[i] : 0;
    sh[tid] = v;
    __syncthreads();
#pragma unroll
    for (int off = 1; off < 1024; off <<= 1) {
        int t = (tid >= off) ? sh[tid - off] : 0;
        __syncthreads();
        sh[tid] += t;
        __syncthreads();
    }
    if (i < N_NODES) rowoff[i] = sh[tid] - v;
    if (tid == 1023) bsum[blockIdx.x] = sh[tid];
}

__global__ void scan2_kernel(int* __restrict__ bsum)
{
    __shared__ int sh[128];
    int tid = threadIdx.x;
    int v = (tid < SCAN_NB) ? bsum[tid] : 0;
    sh[tid] = v;
    __syncthreads();
#pragma unroll
    for (int off = 1; off < 128; off <<= 1) {
        int t = (tid >= off) ? sh[tid - off] : 0;
        __syncthreads();
        sh[tid] += t;
        __syncthreads();
    }
    if (tid < SCAN_NB) bsum[tid] = sh[tid] - v;
}

__global__ void scan3_kernel(int* __restrict__ rowoff, const int* __restrict__ bsum,
                             int* __restrict__ cursor)
{
    int i = blockIdx.x * 1024 + threadIdx.x;
    if (i < N_NODES) {
        int r = rowoff[i] + bsum[blockIdx.x];
        rowoff[i] = r;
        cursor[i] = r;
    }
    if (i == 0) rowoff[N_NODES] = N_EDGES;
}

__global__ void fill_kernel(const int* __restrict__ src, const int* __restrict__ dst,
                            int* __restrict__ cursor, int* __restrict__ csrsrc)
{
    int e = blockIdx.x * 256 + threadIdx.x;
    if (e >= N_EDGES) return;
    int pos = atomicAdd(&cursor[dst[e]], 1);
    csrsrc[pos] = src[e];
}

// ================= CSR gather-reduce (node-range slice) =================
template <int V>   // V = channels/4
__global__ void __launch_bounds__(256) csr_reduce_kernel(
    const float4* __restrict__ x,
    const int* __restrict__ rowoff,
    const int* __restrict__ csrsrc,
    float4* __restrict__ agg,
    int node_base, int node_cnt)
{
    constexpr int J = V / 32;
    int w = (int)((blockIdx.x * 256u + threadIdx.x) >> 5);
    if (w >= node_cnt) return;
    int node = node_base + w;
    int lane = threadIdx.x & 31;

    float4 acc[J];
#pragma unroll
    for (int j = 0; j < J; j++)
        acc[j] = x[(size_t)node * V + j * 32 + lane];

    int b = __ldg(&rowoff[node]);
    int e = __ldg(&rowoff[node + 1]);
    for (; b + 1 < e; b += 2) {
        int s0 = __ldg(&csrsrc[b]);
        int s1 = __ldg(&csrsrc[b + 1]);
#pragma unroll
        for (int j = 0; j < J; j++) {
            float4 v0 = x[(size_t)s0 * V + j * 32 + lane];
            float4 v1 = x[(size_t)s1 * V + j * 32 + lane];
            acc[j] = f4add(acc[j], f4add(v0, v1));
        }
    }
    if (b < e) {
        int s0 = __ldg(&csrsrc[b]);
#pragma unroll
        for (int j = 0; j < J; j++)
            acc[j] = f4add(acc[j], x[(size_t)s0 * V + j * 32 + lane]);
    }
#pragma unroll
    for (int j = 0; j < J; j++)
        agg[(size_t)node * V + j * 32 + lane] = acc[j];
}

// ================= fused 2-layer MLP (tile-base slice) =================
template <int K, int N2, bool OUTER_RELU>
__global__ void __launch_bounds__(512) fused_mlp(
    const float* __restrict__ A,
    const float* __restrict__ Wp1,
    const float* __restrict__ b1v,
    const float* __restrict__ Wp2,
    const float* __restrict__ b2v,
    float* __restrict__ C,
    int tile_base)
{
    constexpr int BM = 128;
    constexpr int GA = K / 32, GB = HID_C / 32;
    constexpr int NT2 = N2 / 64;
    constexpr int NF  = (N2 / 4) / 8;
    constexpr int NPL = NF / 2;
    constexpr int M = N_NODES;
    constexpr int APITCH = 36, HPITCH = 260;
    constexpr int ABUF  = BM * APITCH;
    constexpr int W1OFF = 2 * ABUF;
    constexpr int WBUF1 = 8192;
    constexpr int W2OFF = BM * HPITCH;
    constexpr int WBUF2 = 512 * NT2 * 4;

    extern __shared__ float sm[];
    const uint32_t sbase = smem_u32(sm);

    const int tid  = threadIdx.x;
    const int wid  = tid >> 5;
    const int lane = tid & 31;
    const int gid  = lane >> 2;
    const int tig  = lane & 3;
    const int wm   = wid & 3;
    const int wn   = wid >> 2;
    const int rA   = wm * 32;
    const int m0   = (tile_base + blockIdx.x) * BM;

    float acc[2][8][4];
#pragma unroll
    for (int i = 0; i < 2; i++)
#pragma unroll
        for (int j = 0; j < 8; j++)
#pragma unroll
            for (int c = 0; c < 4; c++) acc[i][j][c] = 0.0f;

    auto loadA = [&](int g) {
        const int s = g & 1;
#pragma unroll
        for (int j = 0; j < 2; j++) {
            int idx = j * 512 + tid;
            int row = idx >> 3, c4 = idx & 7;
            cp_async16(sbase + (uint32_t)(s * ABUF + row * APITCH + c4 * 4) * 4u,
                       A + (size_t)(m0 + row) * K + g * 32 + c4 * 4,
                       (m0 + row) < M);
        }
#pragma unroll
        for (int j = 0; j < 4; j++) {
            int idx = j * 512 + tid;
            cp_async16(sbase + (uint32_t)(W1OFF + s * WBUF1 + idx * 4) * 4u,
                       Wp1 + ((size_t)g * 2048 + idx) * 4, true);
        }
        CP_COMMIT();
    };

    loadA(0);
    for (int g = 0; g < GA; g++) {
        if (g + 1 < GA) { loadA(g + 1); CP_WAIT(1); }
        else            { CP_WAIT(0); }
        __syncthreads();
        const float* as = sm + (g & 1) * ABUF;
        const float* bs = sm + W1OFF + (g & 1) * WBUF1;
#pragma unroll
        for (int ks = 0; ks < 4; ks++) {
            const int k0 = ks * 8;
            uint32_t a[2][4];
#pragma unroll
            for (int mf = 0; mf < 2; mf++) {
                int base = rA + mf * 16;
                a[mf][0] = __float_as_uint(round_tf32(as[(base + gid)     * APITCH + k0 + tig]));
                a[mf][1] = __float_as_uint(round_tf32(as[(base + gid + 8) * APITCH + k0 + tig]));
                a[mf][2] = __float_as_uint(round_tf32(as[(base + gid)     * APITCH + k0 + tig + 4]));
                a[mf][3] = __float_as_uint(round_tf32(as[(base + gid + 8) * APITCH + k0 + tig + 4]));
            }
            uint32_t b[8][2];
#pragma unroll
            for (int p = 0; p < 4; p++) {
                float4 q = *(const float4*)&bs[(((ks * 4 + wn) * 4 + p) * 32 + lane) * 4];
                b[2 * p][0]     = __float_as_uint(q.x);
                b[2 * p][1]     = __float_as_uint(q.y);
                b[2 * p + 1][0] = __float_as_uint(q.z);
                b[2 * p + 1][1] = __float_as_uint(q.w);
            }
#pragma unroll
            for (int mf = 0; mf < 2; mf++)
#pragma unroll
                for (int nf = 0; nf < 8; nf++)
                    mma_tf32(acc[mf][nf], a[mf][0], a[mf][1], a[mf][2], a[mf][3],
                             b[nf][0], b[nf][1]);
        }
        __syncthreads();
    }

    auto loadB = [&](int g) {
        const int s = g & 1;
#pragma unroll
        for (int j = 0; j < NT2; j++) {
            int idx = j * 512 + tid;
            cp_async16(sbase + (uint32_t)(W2OFF + s * WBUF2 + idx * 4) * 4u,
                       Wp2 + ((size_t)g * 512 * NT2 + idx) * 4, true);
        }
        CP_COMMIT();
    };
    loadB(0);

    float* H = sm;
#pragma unroll
    for (int nf = 0; nf < 8; nf++) {
        int col = wn * 64 + nf * 8 + tig * 2;
        float c0 = b1v[col], c1 = b1v[col + 1];
#pragma unroll
        for (int mf = 0; mf < 2; mf++) {
            int r0 = rA + mf * 16 + gid;
            H[(size_t)r0 * HPITCH + col]           = round_tf32(fmaxf(acc[mf][nf][0] + c0, 0.f));
            H[(size_t)r0 * HPITCH + col + 1]       = round_tf32(fmaxf(acc[mf][nf][1] + c1, 0.f));
            H[(size_t)(r0 + 8) * HPITCH + col]     = round_tf32(fmaxf(acc[mf][nf][2] + c0, 0.f));
            H[(size_t)(r0 + 8) * HPITCH + col + 1] = round_tf32(fmaxf(acc[mf][nf][3] + c1, 0.f));
        }
    }
#pragma unroll
    for (int i = 0; i < 2; i++)
#pragma unroll
        for (int j = 0; j < 8; j++)
#pragma unroll
            for (int c = 0; c < 4; c++) acc[i][j][c] = 0.0f;

    const int grp = (NF == 8) ? wn : (wn >> 1);
    for (int g = 0; g < GB; g++) {
        if (g + 1 < GB) { loadB(g + 1); CP_WAIT(1); }
        else            { CP_WAIT(0); }
        __syncthreads();
        const float* bs = sm + W2OFF + (g & 1) * WBUF2;
#pragma unroll
        for (int ks = 0; ks < 4; ks++) {
            const int k0 = g * 32 + ks * 8;
            uint32_t a[2][4];
#pragma unroll
            for (int mf = 0; mf < 2; mf++) {
                int base = rA + mf * 16;
                a[mf][0] = __float_as_uint(H[(size_t)(base + gid)     * HPITCH + k0 + tig]);
                a[mf][1] = __float_as_uint(H[(size_t)(base + gid + 8) * HPITCH + k0 + tig]);
                a[mf][2] = __float_as_uint(H[(size_t)(base + gid)     * HPITCH + k0 + tig + 4]);
                a[mf][3] = __float_as_uint(H[(size_t)(base + gid + 8) * HPITCH + k0 + tig + 4]);
            }
            uint32_t b[8][2];
#pragma unroll
            for (int pl = 0; pl < NPL; pl++) {
                int p = (NF == 8) ? pl : (2 * (wn & 1) + pl);
                float4 q = *(const float4*)&bs[(((ks * NT2 + grp) * 4 + p) * 32 + lane) * 4];
                b[2 * pl][0]     = __float_as_uint(q.x);
                b[2 * pl][1]     = __float_as_uint(q.y);
                b[2 * pl + 1][0] = __float_as_uint(q.z);
                b[2 * pl + 1][1] = __float_as_uint(q.w);
            }
#pragma unroll
            for (int mf = 0; mf < 2; mf++)
#pragma unroll
                for (int nf = 0; nf < NF; nf++)
                    mma_tf32(acc[mf][nf], a[mf][0], a[mf][1], a[mf][2], a[mf][3],
                             b[nf][0], b[nf][1]);
        }
        __syncthreads();
    }

#pragma unroll
    for (int nf = 0; nf < NF; nf++) {
        int col = wn * (N2 / 4) + nf * 8 + tig * 2;
        float c0 = b2v[col], c1 = b2v[col + 1];
#pragma unroll
        for (int mf = 0; mf < 2; mf++) {
            int r0 = m0 + rA + mf * 16 + gid;
            float v0 = acc[mf][nf][0] + c0, v1 = acc[mf][nf][1] + c1;
            float v2 = acc[mf][nf][2] + c0, v3 = acc[mf][nf][3] + c1;
            if (OUTER_RELU) {
                v0 = fmaxf(v0, 0.f); v1 = fmaxf(v1, 0.f);
                v2 = fmaxf(v2, 0.f); v3 = fmaxf(v3, 0.f);
            }
            if (r0 < M)     *(float2*)&C[(size_t)r0 * N2 + col]       = make_float2(v0, v1);
            if (r0 + 8 < M) *(float2*)&C[(size_t)(r0 + 8) * N2 + col] = make_float2(v2, v3);
        }
    }
}

// ================= launch =================
extern "C" void kernel_launch(void* const* d_in, const int* in_sizes, int n_in,
                              void* d_out, int out_size)
{
    const float* x   = (const float*)d_in[0];
    const int*   ei  = (const int*)d_in[1];
    const float* W1a = (const float*)d_in[2];
    const float* b1a = (const float*)d_in[3];
    const float* W2a = (const float*)d_in[4];
    const float* b2a = (const float*)d_in[5];
    const float* W1b = (const float*)d_in[6];
    const float* b1b = (const float*)d_in[7];
    const float* W2b = (const float*)d_in[8];
    const float* b2b = (const float*)d_in[9];
    float* out = (float*)d_out;

    float4 *agg1, *h, *agg2;
    float *Wf1, *Wf2, *Wf3, *Wf4;
    int *cnt, *rowoff, *cursor, *csrsrc, *bsum;
    cudaGetSymbolAddress((void**)&agg1, g_agg1);
    cudaGetSymbolAddress((void**)&h,    g_h);
    cudaGetSymbolAddress((void**)&agg2, g_agg2);
    cudaGetSymbolAddress((void**)&Wf1,  g_Wf1);
    cudaGetSymbolAddress((void**)&Wf2,  g_Wf2);
    cudaGetSymbolAddress((void**)&Wf3,  g_Wf3);
    cudaGetSymbolAddress((void**)&Wf4,  g_Wf4);
    cudaGetSymbolAddress((void**)&cnt,    g_cnt);
    cudaGetSymbolAddress((void**)&rowoff, g_rowoff);
    cudaGetSymbolAddress((void**)&cursor, g_cursor);
    cudaGetSymbolAddress((void**)&csrsrc, g_csrsrc);
    cudaGetSymbolAddress((void**)&bsum,   g_bsum);

    const int* src = ei;
    const int* dst = ei + N_EDGES;
    const int eBlocks = (N_EDGES + 255) / 256;

    // lazy one-time stream/event setup (no device memory allocation)
    static cudaStream_t sA = nullptr, sB = nullptr;
    static cudaEvent_t evFork, evCSR, evH, evJA, evJB;
    static cudaEvent_t ev1[NSLICES], ev2[NSLICES];
    if (!sA) {
        cudaStreamCreateWithFlags(&sA, cudaStreamNonBlocking);
        cudaStreamCreateWithFlags(&sB, cudaStreamNonBlocking);
        cudaEventCreateWithFlags(&evFork, cudaEventDisableTiming);
        cudaEventCreateWithFlags(&evCSR,  cudaEventDisableTiming);
        cudaEventCreateWithFlags(&evH,    cudaEventDisableTiming);
        cudaEventCreateWithFlags(&evJA,   cudaEventDisableTiming);
        cudaEventCreateWithFlags(&evJB,   cudaEventDisableTiming);
        for (int s = 0; s < NSLICES; s++) {
            cudaEventCreateWithFlags(&ev1[s], cudaEventDisableTiming);
            cudaEventCreateWithFlags(&ev2[s], cudaEventDisableTiming);
        }
    }

    const int SM1 = (128 * 260 + 2 * 512 * 4 * 4) * 4;   // 198656
    const int SM2 = (128 * 260 + 2 * 512 * 2 * 4) * 4;   // 165888
    cudaFuncSetAttribute(fused_mlp<IN_C,  HID_C, true >,
                         cudaFuncAttributeMaxDynamicSharedMemorySize, SM1);
    cudaFuncSetAttribute(fused_mlp<HID_C, OUT_C, false>,
                         cudaFuncAttributeMaxDynamicSharedMemorySize, SM2);

    // ---- fork from capture origin (legacy stream) ----
    cudaEventRecord(evFork, 0);
    cudaStreamWaitEvent(sA, evFork, 0);
    cudaStreamWaitEvent(sB, evFork, 0);

    // ---- stream A: CSR build ----
    cudaMemsetAsync(cnt, 0, N_NODES * sizeof(int), sA);
    hist_kernel<<<eBlocks, 256, 0, sA>>>(dst, cnt);
    scan1_kernel<<<SCAN_NB, 1024, 0, sA>>>(cnt, rowoff, bsum);
    scan2_kernel<<<1, 128, 0, sA>>>(bsum);
    scan3_kernel<<<SCAN_NB, 1024, 0, sA>>>(rowoff, bsum, cursor);
    fill_kernel<<<eBlocks, 256, 0, sA>>>(src, dst, cursor, csrsrc);

    // ---- stream B (concurrent with CSR build): weight packs ----
    pack_kernel<IN_C,  HID_C><<<(IN_C * HID_C / 4 + 255) / 256, 256, 0, sB>>>(W1a, Wf1);
    pack_kernel<HID_C, HID_C><<<(HID_C * HID_C / 4 + 255) / 256, 256, 0, sB>>>(W2a, Wf2);
    pack_kernel<HID_C, HID_C><<<(HID_C * HID_C / 4 + 255) / 256, 256, 0, sB>>>(W1b, Wf3);
    pack_kernel<HID_C, OUT_C><<<(HID_C * OUT_C / 4 + 255) / 256, 256, 0, sB>>>(W2b, Wf4);

    // ---- conv1 pipeline: reduce slices on A, mlp slices on B ----
    for (int s = 0; s < NSLICES; s++) {
        int nb = s * TPS * 128;
        int nc = min(N_NODES - nb, TPS * 128);
        int tiles = (nc + 127) / 128;
        csr_reduce_kernel<IN_C / 4><<<(nc * 32 + 255) / 256, 256, 0, sA>>>(
            (const float4*)x, rowoff, csrsrc, agg1, nb, nc);
        cudaEventRecord(ev1[s], sA);
        cudaStreamWaitEvent(sB, ev1[s], 0);
        fused_mlp<IN_C, HID_C, true><<<tiles, 512, SM1, sB>>>(
            (const float*)agg1, Wf1, b1a, Wf2, b2a, (float*)h, s * TPS);
    }
    cudaEventRecord(evH, sB);
    cudaStreamWaitEvent(sA, evH, 0);     // reduce2 needs all of h

    // ---- conv2 pipeline ----
    for (int s = 0; s < NSLICES; s++) {
        int nb = s * TPS * 128;
        int nc = min(N_NODES - nb, TPS * 128);
        int tiles = (nc + 127) / 128;
        csr_reduce_kernel<HID_C / 4><<<(nc * 32 + 255) / 256, 256, 0, sA>>>(
            (const float4*)h, rowoff, csrsrc, agg2, nb, nc);
        cudaEventRecord(ev2[s], sA);
        cudaStreamWaitEvent(sB, ev2[s], 0);
        fused_mlp<HID_C, OUT_C, false><<<tiles, 512, SM2, sB>>>(
            (const float*)agg2, Wf3, b1b, Wf4, b2b, out, s * TPS);
    }

    // ---- join back to origin stream ----
    cudaEventRecord(evJA, sA);
    cudaEventRecord(evJB, sB);
    cudaStreamWaitEvent(0, evJA, 0);
    cudaStreamWaitEvent(0, evJB, 0);
}

// round 11
// speedup vs baseline: 1.0858x; 1.0300x over previous
#include <cuda_runtime.h>
#include <cstdint>

#define N_NODES 100000
#define N_EDGES 1600000
#define IN_C 128
#define HID_C 256
#define OUT_C 128
#define SCAN_NB ((N_NODES + 1023) / 1024)   // 98
#define NSLICES 7
#define TILES_TOTAL ((N_NODES + 127) / 128) // 782
#define TPS 112                              // tiles per slice (<148 => 1 wave + spare SMs)

// ================= scratch =================
__device__ float4 g_agg1[N_NODES * IN_C / 4];
__device__ float4 g_h   [N_NODES * HID_C / 4];
__device__ float4 g_agg2[N_NODES * HID_C / 4];
__device__ float  g_Wf1[IN_C * HID_C];
__device__ float  g_Wf2[HID_C * HID_C];
__device__ float  g_Wf3[HID_C * HID_C];
__device__ float  g_Wf4[HID_C * OUT_C];
__device__ int    g_cnt[N_NODES];
__device__ int    g_rowoff[N_NODES + 1];
__device__ int    g_cursor[N_NODES];
__device__ int    g_csrsrc[N_EDGES];
__device__ int    g_bsum[SCAN_NB];

// ================= helpers =================
__device__ __forceinline__ uint32_t smem_u32(const void* p) {
    uint32_t a;
    asm("{ .reg .u64 t; cvta.to.shared.u64 t, %1; cvt.u32.u64 %0, t; }" : "=r"(a) : "l"(p));
    return a;
}
__device__ __forceinline__ float round_tf32(float x) {
    float r;
    asm("cvt.rna.tf32.f32 %0, %1;" : "=f"(r) : "f"(x));
    return r;
}
__device__ __forceinline__ void cp_async16(uint32_t dst, const void* src, bool pred) {
    int sz = pred ? 16 : 0;
    asm volatile("cp.async.ca.shared.global [%0], [%1], 16, %2;"
                 :: "r"(dst), "l"(src), "r"(sz) : "memory");
}
#define CP_COMMIT() asm volatile("cp.async.commit_group;" ::: "memory")
#define CP_WAIT(n)  asm volatile("cp.async.wait_group %0;" :: "n"(n) : "memory")

__device__ __forceinline__ void mma_tf32(float* d, uint32_t a0, uint32_t a1,
                                         uint32_t a2, uint32_t a3,
                                         uint32_t b0, uint32_t b1) {
    asm volatile(
        "mma.sync.aligned.m16n8k8.row.col.f32.tf32.tf32.f32 "
        "{%0,%1,%2,%3}, {%4,%5,%6,%7}, {%8,%9}, {%0,%1,%2,%3};"
        : "+f"(d[0]), "+f"(d[1]), "+f"(d[2]), "+f"(d[3])
        : "r"(a0), "r"(a1), "r"(a2), "r"(a3), "r"(b0), "r"(b1));
}
__device__ __forceinline__ float4 f4add(float4 a, float4 b) {
    return make_float4(a.x + b.x, a.y + b.y, a.z + b.z, a.w + b.w);
}

// ================= weight fragment-pack =================
template <int K, int NTOT>
__global__ void pack_kernel(const float* __restrict__ W, float* __restrict__ Wf)
{
    constexpr int NT = NTOT / 64;
    constexpr int PER_G = 512 * NT;
    int id = blockIdx.x * 256 + threadIdx.x;
    if (id >= K * NTOT / 4) return;
    int q  = id % PER_G;
    int g  = id / PER_G;
    int lane = q & 31;
    int p    = (q >> 5) & 3;
    int wt   = (q >> 7) % NT;
    int ks   = (q >> 7) / NT;

    int n0 = wt * 64 + 2 * p * 8 + (lane >> 2);
    int k0 = g * 32 + ks * 8 + (lane & 3);
    float4 v;
    v.x = round_tf32(W[(size_t)k0       * NTOT + n0]);
    v.y = round_tf32(W[(size_t)(k0 + 4) * NTOT + n0]);
    v.z = round_tf32(W[(size_t)k0       * NTOT + n0 + 8]);
    v.w = round_tf32(W[(size_t)(k0 + 4) * NTOT + n0 + 8]);
    ((float4*)Wf)[id] = v;
}

// ================= CSR build =================
__global__ void hist_kernel(const int* __restrict__ dst, int* __restrict__ cnt)
{
    int e = blockIdx.x * 256 + threadIdx.x;
    if (e < N_EDGES) atomicAdd(&cnt[dst[e]], 1);
}

__global__ void scan1_kernel(const int* __restrict__ cnt, int* __restrict__ rowoff,
                             int* __restrict__ bsum)
{
    __shared__ int sh[1024];
    int tid = threadIdx.x;
    int i = blockIdx.x * 1024 + tid;
    int v = (i < N_NODES) ? cnt[i] : 0;
    sh[tid] = v;
    __syncthreads();
#pragma unroll
    for (int off = 1; off < 1024; off <<= 1) {
        int t = (tid >= off) ? sh[tid - off] : 0;
        __syncthreads();
        sh[tid] += t;
        __syncthreads();
    }
    if (i < N_NODES) rowoff[i] = sh[tid] - v;
    if (tid == 1023) bsum[blockIdx.x] = sh[tid];
}

__global__ void scan2_kernel(int* __restrict__ bsum)
{
    __shared__ int sh[128];
    int tid = threadIdx.x;
    int v = (tid < SCAN_NB) ? bsum[tid] : 0;
    sh[tid] = v;
    __syncthreads();
#pragma unroll
    for (int off = 1; off < 128; off <<= 1) {
        int t = (tid >= off) ? sh[tid - off] : 0;
        __syncthreads();
        sh[tid] += t;
        __syncthreads();
    }
    if (tid < SCAN_NB) bsum[tid] = sh[tid] - v;
}

__global__ void scan3_kernel(int* __restrict__ rowoff, const int* __restrict__ bsum,
                             int* __restrict__ cursor)
{
    int i = blockIdx.x * 1024 + threadIdx.x;
    if (i < N_NODES) {
        int r = rowoff[i] + bsum[blockIdx.x];
        rowoff[i] = r;
        cursor[i] = r;
    }
    if (i == 0) rowoff[N_NODES] = N_EDGES;
}

__global__ void fill_kernel(const int* __restrict__ src, const int* __restrict__ dst,
                            int* __restrict__ cursor, int* __restrict__ csrsrc)
{
    int e = blockIdx.x * 256 + threadIdx.x;
    if (e >= N_EDGES) return;
    int pos = atomicAdd(&cursor[dst[e]], 1);
    csrsrc[pos] = src[e];
}

// ================= CSR gather-reduce (node-range slice) =================
template <int V>   // V = channels/4
__global__ void __launch_bounds__(256) csr_reduce_kernel(
    const float4* __restrict__ x,
    const int* __restrict__ rowoff,
    const int* __restrict__ csrsrc,
    float4* __restrict__ agg,
    int node_base, int node_cnt)
{
    constexpr int J = V / 32;
    int w = (int)((blockIdx.x * 256u + threadIdx.x) >> 5);
    if (w >= node_cnt) return;
    int node = node_base + w;
    int lane = threadIdx.x & 31;

    float4 acc[J];
#pragma unroll
    for (int j = 0; j < J; j++)
        acc[j] = x[(size_t)node * V + j * 32 + lane];

    int b = __ldg(&rowoff[node]);
    int e = __ldg(&rowoff[node + 1]);
    for (; b + 1 < e; b += 2) {
        int s0 = __ldg(&csrsrc[b]);
        int s1 = __ldg(&csrsrc[b + 1]);
#pragma unroll
        for (int j = 0; j < J; j++) {
            float4 v0 = x[(size_t)s0 * V + j * 32 + lane];
            float4 v1 = x[(size_t)s1 * V + j * 32 + lane];
            acc[j] = f4add(acc[j], f4add(v0, v1));
        }
    }
    if (b < e) {
        int s0 = __ldg(&csrsrc[b]);
#pragma unroll
        for (int j = 0; j < J; j++)
            acc[j] = f4add(acc[j], x[(size_t)s0 * V + j * 32 + lane]);
    }
#pragma unroll
    for (int j = 0; j < J; j++)
        agg[(size_t)node * V + j * 32 + lane] = acc[j];
}

// ================= fused 2-layer MLP (tile-base slice) =================
template <int K, int N2, bool OUTER_RELU>
__global__ void __launch_bounds__(512) fused_mlp(
    const float* __restrict__ A,
    const float* __restrict__ Wp1,
    const float* __restrict__ b1v,
    const float* __restrict__ Wp2,
    const float* __restrict__ b2v,
    float* __restrict__ C,
    int tile_base)
{
    constexpr int BM = 128;
    constexpr int GA = K / 32, GB = HID_C / 32;
    constexpr int NT2 = N2 / 64;
    constexpr int NF  = (N2 / 4) / 8;
    constexpr int NPL = NF / 2;
    constexpr int M = N_NODES;
    constexpr int APITCH = 36, HPITCH = 260;
    constexpr int ABUF  = BM * APITCH;
    constexpr int W1OFF = 2 * ABUF;
    constexpr int WBUF1 = 8192;
    constexpr int W2OFF = BM * HPITCH;
    constexpr int WBUF2 = 512 * NT2 * 4;

    extern __shared__ float sm[];
    const uint32_t sbase = smem_u32(sm);

    const int tid  = threadIdx.x;
    const int wid  = tid >> 5;
    const int lane = tid & 31;
    const int gid  = lane >> 2;
    const int tig  = lane & 3;
    const int wm   = wid & 3;
    const int wn   = wid >> 2;
    const int rA   = wm * 32;
    const int m0   = (tile_base + blockIdx.x) * BM;

    float acc[2][8][4];
#pragma unroll
    for (int i = 0; i < 2; i++)
#pragma unroll
        for (int j = 0; j < 8; j++)
#pragma unroll
            for (int c = 0; c < 4; c++) acc[i][j][c] = 0.0f;

    auto loadA = [&](int g) {
        const int s = g & 1;
#pragma unroll
        for (int j = 0; j < 2; j++) {
            int idx = j * 512 + tid;
            int row = idx >> 3, c4 = idx & 7;
            cp_async16(sbase + (uint32_t)(s * ABUF + row * APITCH + c4 * 4) * 4u,
                       A + (size_t)(m0 + row) * K + g * 32 + c4 * 4,
                       (m0 + row) < M);
        }
#pragma unroll
        for (int j = 0; j < 4; j++) {
            int idx = j * 512 + tid;
            cp_async16(sbase + (uint32_t)(W1OFF + s * WBUF1 + idx * 4) * 4u,
                       Wp1 + ((size_t)g * 2048 + idx) * 4, true);
        }
        CP_COMMIT();
    };

    loadA(0);
    for (int g = 0; g < GA; g++) {
        if (g + 1 < GA) { loadA(g + 1); CP_WAIT(1); }
        else            { CP_WAIT(0); }
        __syncthreads();
        const float* as = sm + (g & 1) * ABUF;
        const float* bs = sm + W1OFF + (g & 1) * WBUF1;
#pragma unroll
        for (int ks = 0; ks < 4; ks++) {
            const int k0 = ks * 8;
            uint32_t a[2][4];
#pragma unroll
            for (int mf = 0; mf < 2; mf++) {
                int base = rA + mf * 16;
                a[mf][0] = __float_as_uint(round_tf32(as[(base + gid)     * APITCH + k0 + tig]));
                a[mf][1] = __float_as_uint(round_tf32(as[(base + gid + 8) * APITCH + k0 + tig]));
                a[mf][2] = __float_as_uint(round_tf32(as[(base + gid)     * APITCH + k0 + tig + 4]));
                a[mf][3] = __float_as_uint(round_tf32(as[(base + gid + 8) * APITCH + k0 + tig + 4]));
            }
            uint32_t b[8][2];
#pragma unroll
            for (int p = 0; p < 4; p++) {
                float4 q = *(const float4*)&bs[(((ks * 4 + wn) * 4 + p) * 32 + lane) * 4];
                b[2 * p][0]     = __float_as_uint(q.x);
                b[2 * p][1]     = __float_as_uint(q.y);
                b[2 * p + 1][0] = __float_as_uint(q.z);
                b[2 * p + 1][1] = __float_as_uint(q.w);
            }
#pragma unroll
            for (int mf = 0; mf < 2; mf++)
#pragma unroll
                for (int nf = 0; nf < 8; nf++)
                    mma_tf32(acc[mf][nf], a[mf][0], a[mf][1], a[mf][2], a[mf][3],
                             b[nf][0], b[nf][1]);
        }
        __syncthreads();
    }

    auto loadB = [&](int g) {
        const int s = g & 1;
#pragma unroll
        for (int j = 0; j < NT2; j++) {
            int idx = j * 512 + tid;
            cp_async16(sbase + (uint32_t)(W2OFF + s * WBUF2 + idx * 4) * 4u,
                       Wp2 + ((size_t)g * 512 * NT2 + idx) * 4, true);
        }
        CP_COMMIT();
    };
    loadB(0);

    float* H = sm;
#pragma unroll
    for (int nf = 0; nf < 8; nf++) {
        int col = wn * 64 + nf * 8 + tig * 2;
        float c0 = b1v[col], c1 = b1v[col + 1];
#pragma unroll
        for (int mf = 0; mf < 2; mf++) {
            int r0 = rA + mf * 16 + gid;
            H[(size_t)r0 * HPITCH + col]           = round_tf32(fmaxf(acc[mf][nf][0] + c0, 0.f));
            H[(size_t)r0 * HPITCH + col + 1]       = round_tf32(fmaxf(acc[mf][nf][1] + c1, 0.f));
            H[(size_t)(r0 + 8) * HPITCH + col]     = round_tf32(fmaxf(acc[mf][nf][2] + c0, 0.f));
            H[(size_t)(r0 + 8) * HPITCH + col + 1] = round_tf32(fmaxf(acc[mf][nf][3] + c1, 0.f));
        }
    }
#pragma unroll
    for (int i = 0; i < 2; i++)
#pragma unroll
        for (int j = 0; j < 8; j++)
#pragma unroll
            for (int c = 0; c < 4; c++) acc[i][j][c] = 0.0f;

    const int grp = (NF == 8) ? wn : (wn >> 1);
    for (int g = 0; g < GB; g++) {
        if (g + 1 < GB) { loadB(g + 1); CP_WAIT(1); }
        else            { CP_WAIT(0); }
        __syncthreads();
        const float* bs = sm + W2OFF + (g & 1) * WBUF2;
#pragma unroll
        for (int ks = 0; ks < 4; ks++) {
            const int k0 = g * 32 + ks * 8;
            uint32_t a[2][4];
#pragma unroll
            for (int mf = 0; mf < 2; mf++) {
                int base = rA + mf * 16;
                a[mf][0] = __float_as_uint(H[(size_t)(base + gid)     * HPITCH + k0 + tig]);
                a[mf][1] = __float_as_uint(H[(size_t)(base + gid + 8) * HPITCH + k0 + tig]);
                a[mf][2] = __float_as_uint(H[(size_t)(base + gid)     * HPITCH + k0 + tig + 4]);
                a[mf][3] = __float_as_uint(H[(size_t)(base + gid + 8) * HPITCH + k0 + tig + 4]);
            }
            uint32_t b[8][2];
#pragma unroll
            for (int pl = 0; pl < NPL; pl++) {
                int p = (NF == 8) ? pl : (2 * (wn & 1) + pl);
                float4 q = *(const float4*)&bs[(((ks * NT2 + grp) * 4 + p) * 32 + lane) * 4];
                b[2 * pl][0]     = __float_as_uint(q.x);
                b[2 * pl][1]     = __float_as_uint(q.y);
                b[2 * pl + 1][0] = __float_as_uint(q.z);
                b[2 * pl + 1][1] = __float_as_uint(q.w);
            }
#pragma unroll
            for (int mf = 0; mf < 2; mf++)
#pragma unroll
                for (int nf = 0; nf < NF; nf++)
                    mma_tf32(acc[mf][nf], a[mf][0], a[mf][1], a[mf][2], a[mf][3],
                             b[nf][0], b[nf][1]);
        }
        __syncthreads();
    }

#pragma unroll
    for (int nf = 0; nf < NF; nf++) {
        int col = wn * (N2 / 4) + nf * 8 + tig * 2;
        float c0 = b2v[col], c1 = b2v[col + 1];
#pragma unroll
        for (int mf = 0; mf < 2; mf++) {
            int r0 = m0 + rA + mf * 16 + gid;
            float v0 = acc[mf][nf][0] + c0, v1 = acc[mf][nf][1] + c1;
            float v2 = acc[mf][nf][2] + c0, v3 = acc[mf][nf][3] + c1;
            if (OUTER_RELU) {
                v0 = fmaxf(v0, 0.f); v1 = fmaxf(v1, 0.f);
                v2 = fmaxf(v2, 0.f); v3 = fmaxf(v3, 0.f);
            }
            if (r0 < M)     *(float2*)&C[(size_t)r0 * N2 + col]       = make_float2(v0, v1);
            if (r0 + 8 < M) *(float2*)&C[(size_t)(r0 + 8) * N2 + col] = make_float2(v2, v3);
        }
    }
}

// ================= launch =================
extern "C" void kernel_launch(void* const* d_in, const int* in_sizes, int n_in,
                              void* d_out, int out_size)
{
    const float* x   = (const float*)d_in[0];
    const int*   ei  = (const int*)d_in[1];
    const float* W1a = (const float*)d_in[2];
    const float* b1a = (const float*)d_in[3];
    const float* W2a = (const float*)d_in[4];
    const float* b2a = (const float*)d_in[5];
    const float* W1b = (const float*)d_in[6];
    const float* b1b = (const float*)d_in[7];
    const float* W2b = (const float*)d_in[8];
    const float* b2b = (const float*)d_in[9];
    float* out = (float*)d_out;

    float4 *agg1, *h, *agg2;
    float *Wf1, *Wf2, *Wf3, *Wf4;
    int *cnt, *rowoff, *cursor, *csrsrc, *bsum;
    cudaGetSymbolAddress((void**)&agg1, g_agg1);
    cudaGetSymbolAddress((void**)&h,    g_h);
    cudaGetSymbolAddress((void**)&agg2, g_agg2);
    cudaGetSymbolAddress((void**)&Wf1,  g_Wf1);
    cudaGetSymbolAddress((void**)&Wf2,  g_Wf2);
    cudaGetSymbolAddress((void**)&Wf3,  g_Wf3);
    cudaGetSymbolAddress((void**)&Wf4,  g_Wf4);
    cudaGetSymbolAddress((void**)&cnt,    g_cnt);
    cudaGetSymbolAddress((void**)&rowoff, g_rowoff);
    cudaGetSymbolAddress((void**)&cursor, g_cursor);
    cudaGetSymbolAddress((void**)&csrsrc, g_csrsrc);
    cudaGetSymbolAddress((void**)&bsum,   g_bsum);

    const int* src = ei;
    const int* dst = ei + N_EDGES;
    const int eBlocks = (N_EDGES + 255) / 256;

    // lazy one-time stream/event setup; sB (MLP) = HIGH priority, sA (memory) = LOW
    static cudaStream_t sA = nullptr, sB = nullptr;
    static cudaEvent_t evFork, evH, evJA, evJB;
    static cudaEvent_t ev1[NSLICES], ev2[NSLICES];
    if (!sA) {
        int prLow, prHigh;
        cudaDeviceGetStreamPriorityRange(&prLow, &prHigh);
        cudaStreamCreateWithPriority(&sA, cudaStreamNonBlocking, prLow);
        cudaStreamCreateWithPriority(&sB, cudaStreamNonBlocking, prHigh);
        cudaEventCreateWithFlags(&evFork, cudaEventDisableTiming);
        cudaEventCreateWithFlags(&evH,    cudaEventDisableTiming);
        cudaEventCreateWithFlags(&evJA,   cudaEventDisableTiming);
        cudaEventCreateWithFlags(&evJB,   cudaEventDisableTiming);
        for (int s = 0; s < NSLICES; s++) {
            cudaEventCreateWithFlags(&ev1[s], cudaEventDisableTiming);
            cudaEventCreateWithFlags(&ev2[s], cudaEventDisableTiming);
        }
    }

    const int SM1 = (128 * 260 + 2 * 512 * 4 * 4) * 4;   // 198656
    const int SM2 = (128 * 260 + 2 * 512 * 2 * 4) * 4;   // 165888
    cudaFuncSetAttribute(fused_mlp<IN_C,  HID_C, true >,
                         cudaFuncAttributeMaxDynamicSharedMemorySize, SM1);
    cudaFuncSetAttribute(fused_mlp<HID_C, OUT_C, false>,
                         cudaFuncAttributeMaxDynamicSharedMemorySize, SM2);

    // ---- fork ----
    cudaEventRecord(evFork, 0);
    cudaStreamWaitEvent(sA, evFork, 0);
    cudaStreamWaitEvent(sB, evFork, 0);

    // ---- stream A: CSR build ----
    cudaMemsetAsync(cnt, 0, N_NODES * sizeof(int), sA);
    hist_kernel<<<eBlocks, 256, 0, sA>>>(dst, cnt);
    scan1_kernel<<<SCAN_NB, 1024, 0, sA>>>(cnt, rowoff, bsum);
    scan2_kernel<<<1, 128, 0, sA>>>(bsum);
    scan3_kernel<<<SCAN_NB, 1024, 0, sA>>>(rowoff, bsum, cursor);
    fill_kernel<<<eBlocks, 256, 0, sA>>>(src, dst, cursor, csrsrc);

    // ---- stream B (concurrent with CSR build): weight packs ----
    pack_kernel<IN_C,  HID_C><<<(IN_C * HID_C / 4 + 255) / 256, 256, 0, sB>>>(W1a, Wf1);
    pack_kernel<HID_C, HID_C><<<(HID_C * HID_C / 4 + 255) / 256, 256, 0, sB>>>(W2a, Wf2);
    pack_kernel<HID_C, HID_C><<<(HID_C * HID_C / 4 + 255) / 256, 256, 0, sB>>>(W1b, Wf3);
    pack_kernel<HID_C, OUT_C><<<(HID_C * OUT_C / 4 + 255) / 256, 256, 0, sB>>>(W2b, Wf4);

    // ---- conv1 pipeline: reduce slices on A (low prio), mlp slices on B (high prio) ----
    for (int s = 0; s < NSLICES; s++) {
        int nb = s * TPS * 128;
        int nc = N_NODES - nb; if (nc > TPS * 128) nc = TPS * 128;
        if (nc <= 0) break;
        int tiles = (nc + 127) / 128;
        csr_reduce_kernel<IN_C / 4><<<(nc * 32 + 255) / 256, 256, 0, sA>>>(
            (const float4*)x, rowoff, csrsrc, agg1, nb, nc);
        cudaEventRecord(ev1[s], sA);
        cudaStreamWaitEvent(sB, ev1[s], 0);
        fused_mlp<IN_C, HID_C, true><<<tiles, 512, SM1, sB>>>(
            (const float*)agg1, Wf1, b1a, Wf2, b2a, (float*)h, s * TPS);
    }
    cudaEventRecord(evH, sB);
    cudaStreamWaitEvent(sA, evH, 0);     // reduce2 needs all of h

    // ---- conv2 pipeline ----
    for (int s = 0; s < NSLICES; s++) {
        int nb = s * TPS * 128;
        int nc = N_NODES - nb; if (nc > TPS * 128) nc = TPS * 128;
        if (nc <= 0) break;
        int tiles = (nc + 127) / 128;
        csr_reduce_kernel<HID_C / 4><<<(nc * 32 + 255) / 256, 256, 0, sA>>>(
            (const float4*)h, rowoff, csrsrc, agg2, nb, nc);
        cudaEventRecord(ev2[s], sA);
        cudaStreamWaitEvent(sB, ev2[s], 0);
        fused_mlp<HID_C, OUT_C, false><<<tiles, 512, SM2, sB>>>(
            (const float*)agg2, Wf3, b1b, Wf4, b2b, out, s * TPS);
    }

    // ---- join ----
    cudaEventRecord(evJA, sA);
    cudaEventRecord(evJB, sB);
    cudaStreamWaitEvent(0, evJA, 0);
    cudaStreamWaitEvent(0, evJB, 0);
}

// round 12
// speedup vs baseline: 1.5828x; 1.4578x over previous
#include <cuda_runtime.h>
#include <cuda_fp16.h>
#include <cstdint>

#define N_NODES 100000
#define N_EDGES 1600000
#define IN_C 128
#define HID_C 256
#define OUT_C 128
#define SCAN_NB ((N_NODES + 1023) / 1024)   // 98

// ================= scratch =================
__device__ __half  g_agg1[N_NODES * IN_C];       // fp16 aggregated input (conv1)
__device__ float4  g_h   [N_NODES * HID_C / 4];  // conv1 output (fp32, relu)
__device__ __half  g_agg2[N_NODES * HID_C];      // fp16 aggregated input (conv2)
__device__ __half  g_Wf1[IN_C * HID_C];          // fragment-packed fp16 weights
__device__ __half  g_Wf2[HID_C * HID_C];
__device__ __half  g_Wf3[HID_C * HID_C];
__device__ __half  g_Wf4[HID_C * OUT_C];
__device__ int     g_cnt[N_NODES];
__device__ int     g_rowoff[N_NODES + 1];
__device__ int     g_cursor[N_NODES];
__device__ int     g_csrsrc[N_EDGES];
__device__ int     g_bsum[SCAN_NB];

// ================= helpers =================
__device__ __forceinline__ uint32_t smem_u32(const void* p) {
    uint32_t a;
    asm("{ .reg .u64 t; cvta.to.shared.u64 t, %1; cvt.u32.u64 %0, t; }" : "=r"(a) : "l"(p));
    return a;
}
__device__ __forceinline__ void cp_async16(uint32_t dst, const void* src, bool pred) {
    int sz = pred ? 16 : 0;
    asm volatile("cp.async.ca.shared.global [%0], [%1], 16, %2;"
                 :: "r"(dst), "l"(src), "r"(sz) : "memory");
}
#define CP_COMMIT() asm volatile("cp.async.commit_group;" ::: "memory")
#define CP_WAIT(n)  asm volatile("cp.async.wait_group %0;" :: "n"(n) : "memory")

__device__ __forceinline__ void mma_f16(float* d, uint32_t a0, uint32_t a1,
                                        uint32_t a2, uint32_t a3,
                                        uint32_t b0, uint32_t b1) {
    asm volatile(
        "mma.sync.aligned.m16n8k16.row.col.f32.f16.f16.f32 "
        "{%0,%1,%2,%3}, {%4,%5,%6,%7}, {%8,%9}, {%0,%1,%2,%3};"
        : "+f"(d[0]), "+f"(d[1]), "+f"(d[2]), "+f"(d[3])
        : "r"(a0), "r"(a1), "r"(a2), "r"(a3), "r"(b0), "r"(b1));
}
__device__ __forceinline__ float4 f4add(float4 a, float4 b) {
    return make_float4(a.x + b.x, a.y + b.y, a.z + b.z, a.w + b.w);
}
__device__ __forceinline__ uint32_t pack_h2(float lo, float hi) {
    __half2 h = __floats2half2_rn(lo, hi);
    return *(uint32_t*)&h;
}

// ================= weight fragment-pack (fp16) =================
// Per 32-k chunk g: [ks(2)][wt(NT)][p(4)][lane(32)] x uint4 (8 halves)
// uint4 = { h2(W[k0][n0],W[k0+1][n0]), h2(W[k0+8][n0],W[k0+9][n0]),
//           h2(W[k0][n0+8],...),       h2(W[k0+8][n0+8],...) }
// n0 = wt*64 + 2p*8 + lane/4 ; k0 = g*32 + ks*16 + 2*(lane%4)
template <int K, int NTOT>
__global__ void pack_kernel(const float* __restrict__ W, __half* __restrict__ Wf)
{
    constexpr int NT = NTOT / 64;
    constexpr int PER_G = 4 * NTOT;             // uint4s per 32-k chunk
    int id = blockIdx.x * 256 + threadIdx.x;
    if (id >= K * NTOT / 8) return;
    int q  = id % PER_G;
    int g  = id / PER_G;
    int lane = q & 31;
    int p    = (q >> 5) & 3;
    int rest = q >> 7;
    int wt   = rest % NT;
    int ks   = rest / NT;

    int gid = lane >> 2, tig = lane & 3;
    int n0 = wt * 64 + 2 * p * 8 + gid;
    int k0 = g * 32 + ks * 16 + tig * 2;

    uint4 v;
    v.x = pack_h2(W[(size_t)k0       * NTOT + n0],     W[(size_t)(k0 + 1) * NTOT + n0]);
    v.y = pack_h2(W[(size_t)(k0 + 8) * NTOT + n0],     W[(size_t)(k0 + 9) * NTOT + n0]);
    v.z = pack_h2(W[(size_t)k0       * NTOT + n0 + 8], W[(size_t)(k0 + 1) * NTOT + n0 + 8]);
    v.w = pack_h2(W[(size_t)(k0 + 8) * NTOT + n0 + 8], W[(size_t)(k0 + 9) * NTOT + n0 + 8]);
    *(uint4*)&Wf[(size_t)id * 8] = v;
}

// ================= CSR build =================
__global__ void hist_kernel(const int* __restrict__ dst, int* __restrict__ cnt)
{
    int e = blockIdx.x * 256 + threadIdx.x;
    if (e < N_EDGES) atomicAdd(&cnt[dst[e]], 1);
}

__global__ void scan1_kernel(const int* __restrict__ cnt, int* __restrict__ rowoff,
                             int* __restrict__ bsum)
{
    __shared__ int sh[1024];
    int tid = threadIdx.x;
    int i = blockIdx.x * 1024 + tid;
    int v = (i < N_NODES) ? cnt[i] : 0;
    sh[tid] = v;
    __syncthreads();
#pragma unroll
    for (int off = 1; off < 1024; off <<= 1) {
        int t = (tid >= off) ? sh[tid - off] : 0;
        __syncthreads();
        sh[tid] += t;
        __syncthreads();
    }
    if (i < N_NODES) rowoff[i] = sh[tid] - v;
    if (tid == 1023) bsum[blockIdx.x] = sh[tid];
}

__global__ void scan2_kernel(int* __restrict__ bsum)
{
    __shared__ int sh[128];
    int tid = threadIdx.x;
    int v = (tid < SCAN_NB) ? bsum[tid] : 0;
    sh[tid] = v;
    __syncthreads();
#pragma unroll
    for (int off = 1; off < 128; off <<= 1) {
        int t = (tid >= off) ? sh[tid - off] : 0;
        __syncthreads();
        sh[tid] += t;
        __syncthreads();
    }
    if (tid < SCAN_NB) bsum[tid] = sh[tid] - v;
}

__global__ void scan3_kernel(int* __restrict__ rowoff, const int* __restrict__ bsum,
                             int* __restrict__ cursor)
{
    int i = blockIdx.x * 1024 + threadIdx.x;
    if (i < N_NODES) {
        int r = rowoff[i] + bsum[blockIdx.x];
        rowoff[i] = r;
        cursor[i] = r;
    }
    if (i == 0) rowoff[N_NODES] = N_EDGES;
}

__global__ void fill_kernel(const int* __restrict__ src, const int* __restrict__ dst,
                            int* __restrict__ cursor, int* __restrict__ csrsrc)
{
    int e = blockIdx.x * 256 + threadIdx.x;
    if (e >= N_EDGES) return;
    int pos = atomicAdd(&cursor[dst[e]], 1);
    csrsrc[pos] = src[e];
}

// ================= CSR gather-reduce: fp32 accumulate, fp16 store =================
template <int V>   // V = channels/4
__global__ void __launch_bounds__(256) csr_reduce_kernel(
    const float4* __restrict__ x,
    const int* __restrict__ rowoff,
    const int* __restrict__ csrsrc,
    __half* __restrict__ agg)
{
    constexpr int J = V / 32;
    constexpr int C = V * 4;
    int node = (int)((blockIdx.x * 256u + threadIdx.x) >> 5);
    if (node >= N_NODES) return;
    int lane = threadIdx.x & 31;

    float4 acc[J];
#pragma unroll
    for (int j = 0; j < J; j++)
        acc[j] = x[(size_t)node * V + j * 32 + lane];

    int b = __ldg(&rowoff[node]);
    int e = __ldg(&rowoff[node + 1]);
    for (; b + 1 < e; b += 2) {
        int s0 = __ldg(&csrsrc[b]);
        int s1 = __ldg(&csrsrc[b + 1]);
#pragma unroll
        for (int j = 0; j < J; j++) {
            float4 v0 = x[(size_t)s0 * V + j * 32 + lane];
            float4 v1 = x[(size_t)s1 * V + j * 32 + lane];
            acc[j] = f4add(acc[j], f4add(v0, v1));
        }
    }
    if (b < e) {
        int s0 = __ldg(&csrsrc[b]);
#pragma unroll
        for (int j = 0; j < J; j++)
            acc[j] = f4add(acc[j], x[(size_t)s0 * V + j * 32 + lane]);
    }
#pragma unroll
    for (int j = 0; j < J; j++) {
        uint2 u;
        u.x = pack_h2(acc[j].x, acc[j].y);
        u.y = pack_h2(acc[j].z, acc[j].w);
        *(uint2*)&agg[(size_t)node * C + (j * 32 + lane) * 4] = u;
    }
}

// ================= fused 2-layer MLP, fp16 MMA =================
// C[M,N2] = act( relu(A[M,K] @ W1[K,256] + b1) @ W2[256,N2] + b2 )
// BM=128, 512 threads = 16 warps (4m x 4n). fp16 A/H tiles in smem.
template <int K, int N2, bool OUTER_RELU>
__global__ void __launch_bounds__(512) fused_mlp(
    const __half* __restrict__ A,      // [M, K] fp16
    const __half* __restrict__ Wp1,    // packed fp16 [K x 256]
    const float* __restrict__ b1v,
    const __half* __restrict__ Wp2,    // packed fp16 [256 x N2]
    const float* __restrict__ b2v,
    float* __restrict__ C)
{
    constexpr int BM = 128;
    constexpr int GA = K / 32, GB = HID_C / 32;
    constexpr int NT2 = N2 / 64;                 // 4 or 2
    constexpr int NF  = N2 / 32;                 // 8 or 4
    constexpr int NPL = NF / 2;
    constexpr int M = N_NODES;
    constexpr int AP = 40, HP = 264;             // pitches in halves
    constexpr int ABUF  = BM * AP;               // 5120 halves / buffer
    constexpr int W1OFF = 2 * ABUF;              // 10240
    constexpr int WBUF1 = 8192;                  // halves (32k x 256n)
    constexpr int W2OFF = BM * HP;               // 33792 (H region, halves)
    constexpr int WBUF2 = 32 * N2;               // halves

    extern __shared__ __half smh[];
    const uint32_t sbase = smem_u32(smh);

    const int tid  = threadIdx.x;
    const int wid  = tid >> 5;
    const int lane = tid & 31;
    const int gid  = lane >> 2;
    const int tig  = lane & 3;
    const int wm   = wid & 3;
    const int wn   = wid >> 2;
    const int rA   = wm * 32;
    const int m0   = blockIdx.x * BM;

    float acc[2][8][4];
#pragma unroll
    for (int i = 0; i < 2; i++)
#pragma unroll
        for (int j = 0; j < 8; j++)
#pragma unroll
            for (int c = 0; c < 4; c++) acc[i][j][c] = 0.0f;

    // ---- loaders ----
    auto loadA = [&](int g) {
        const int s = g & 1;
        {   // A: 128 rows x 32 halves = 512 x 16B chunks (1 per thread)
            int row = tid >> 2, c4 = tid & 3;
            cp_async16(sbase + (uint32_t)(s * ABUF + row * AP + c4 * 8) * 2u,
                       A + (size_t)(m0 + row) * K + g * 32 + c4 * 8,
                       (m0 + row) < M);
        }
#pragma unroll
        for (int j = 0; j < 2; j++) {   // W1 chunk: 16 KB = 1024 x 16B
            int idx = j * 512 + tid;
            cp_async16(sbase + (uint32_t)(W1OFF + s * WBUF1 + idx * 8) * 2u,
                       Wp1 + (size_t)g * WBUF1 + idx * 8, true);
        }
        CP_COMMIT();
    };
    auto loadB = [&](int g) {
        const int s = g & 1;
#pragma unroll
        for (int j = 0; j < WBUF2 / 8 / 512; j++) {
            int idx = j * 512 + tid;
            cp_async16(sbase + (uint32_t)(W2OFF + s * WBUF2 + idx * 8) * 2u,
                       Wp2 + (size_t)g * WBUF2 + idx * 8, true);
        }
        CP_COMMIT();
    };

    // ---- phase A: Hacc = A @ W1 ----
    loadA(0);
    for (int g = 0; g < GA; g++) {
        if (g + 1 < GA) { loadA(g + 1); CP_WAIT(1); }
        else            { CP_WAIT(0); }
        __syncthreads();
        const __half* ah = smh + (g & 1) * ABUF;
        const float4* bf = (const float4*)(smh + W1OFF + (g & 1) * WBUF1);
#pragma unroll
        for (int ks = 0; ks < 2; ks++) {
            const int k0 = ks * 16 + 2 * tig;
            uint32_t a[2][4];
#pragma unroll
            for (int mf = 0; mf < 2; mf++) {
                int base = rA + mf * 16;
                a[mf][0] = *(const uint32_t*)&ah[(base + gid)     * AP + k0];
                a[mf][1] = *(const uint32_t*)&ah[(base + gid + 8) * AP + k0];
                a[mf][2] = *(const uint32_t*)&ah[(base + gid)     * AP + k0 + 8];
                a[mf][3] = *(const uint32_t*)&ah[(base + gid + 8) * AP + k0 + 8];
            }
            uint32_t b[8][2];
#pragma unroll
            for (int p = 0; p < 4; p++) {
                float4 q = bf[((ks * 4 + wn) * 4 + p) * 32 + lane];
                b[2 * p][0]     = __float_as_uint(q.x);
                b[2 * p][1]     = __float_as_uint(q.y);
                b[2 * p + 1][0] = __float_as_uint(q.z);
                b[2 * p + 1][1] = __float_as_uint(q.w);
            }
#pragma unroll
            for (int mf = 0; mf < 2; mf++)
#pragma unroll
                for (int nf = 0; nf < 8; nf++)
                    mma_f16(acc[mf][nf], a[mf][0], a[mf][1], a[mf][2], a[mf][3],
                            b[nf][0], b[nf][1]);
        }
        __syncthreads();
    }

    loadB(0);   // overlaps H spill

    // ---- spill H = fp16(relu(acc + b1)) into smem (overlays A/W1 region) ----
#pragma unroll
    for (int nf = 0; nf < 8; nf++) {
        int col = wn * 64 + nf * 8 + tig * 2;
        float c0 = b1v[col], c1 = b1v[col + 1];
#pragma unroll
        for (int mf = 0; mf < 2; mf++) {
            int r0 = rA + mf * 16 + gid;
            *(uint32_t*)&smh[(size_t)r0 * HP + col] =
                pack_h2(fmaxf(acc[mf][nf][0] + c0, 0.f), fmaxf(acc[mf][nf][1] + c1, 0.f));
            *(uint32_t*)&smh[(size_t)(r0 + 8) * HP + col] =
                pack_h2(fmaxf(acc[mf][nf][2] + c0, 0.f), fmaxf(acc[mf][nf][3] + c1, 0.f));
        }
    }
#pragma unroll
    for (int i = 0; i < 2; i++)
#pragma unroll
        for (int j = 0; j < 8; j++)
#pragma unroll
            for (int c = 0; c < 4; c++) acc[i][j][c] = 0.0f;

    // ---- phase 4: OUT = H @ W2 ----
    const int grp = (NF == 8) ? wn : (wn >> 1);
    for (int g = 0; g < GB; g++) {
        if (g + 1 < GB) { loadB(g + 1); CP_WAIT(1); }
        else            { CP_WAIT(0); }
        __syncthreads();                     // g==0: also orders H spill before reads
        const float4* bf = (const float4*)(smh + W2OFF + (g & 1) * WBUF2);
#pragma unroll
        for (int ks = 0; ks < 2; ks++) {
            const int k0 = g * 32 + ks * 16 + 2 * tig;
            uint32_t a[2][4];
#pragma unroll
            for (int mf = 0; mf < 2; mf++) {
                int base = rA + mf * 16;
                a[mf][0] = *(const uint32_t*)&smh[(size_t)(base + gid)     * HP + k0];
                a[mf][1] = *(const uint32_t*)&smh[(size_t)(base + gid + 8) * HP + k0];
                a[mf][2] = *(const uint32_t*)&smh[(size_t)(base + gid)     * HP + k0 + 8];
                a[mf][3] = *(const uint32_t*)&smh[(size_t)(base + gid + 8) * HP + k0 + 8];
            }
            uint32_t b[8][2];
#pragma unroll
            for (int pl = 0; pl < NPL; pl++) {
                int p = (NF == 8) ? pl : (2 * (wn & 1) + pl);
                float4 q = bf[((ks * NT2 + grp) * 4 + p) * 32 + lane];
                b[2 * pl][0]     = __float_as_uint(q.x);
                b[2 * pl][1]     = __float_as_uint(q.y);
                b[2 * pl + 1][0] = __float_as_uint(q.z);
                b[2 * pl + 1][1] = __float_as_uint(q.w);
            }
#pragma unroll
            for (int mf = 0; mf < 2; mf++)
#pragma unroll
                for (int nf = 0; nf < NF; nf++)
                    mma_f16(acc[mf][nf], a[mf][0], a[mf][1], a[mf][2], a[mf][3],
                            b[nf][0], b[nf][1]);
        }
        __syncthreads();
    }

    // ---- epilogue: fp32 out ----
#pragma unroll
    for (int nf = 0; nf < NF; nf++) {
        int col = wn * (N2 / 4) + nf * 8 + tig * 2;
        float c0 = b2v[col], c1 = b2v[col + 1];
#pragma unroll
        for (int mf = 0; mf < 2; mf++) {
            int r0 = m0 + rA + mf * 16 + gid;
            float v0 = acc[mf][nf][0] + c0, v1 = acc[mf][nf][1] + c1;
            float v2 = acc[mf][nf][2] + c0, v3 = acc[mf][nf][3] + c1;
            if (OUTER_RELU) {
                v0 = fmaxf(v0, 0.f); v1 = fmaxf(v1, 0.f);
                v2 = fmaxf(v2, 0.f); v3 = fmaxf(v3, 0.f);
            }
            if (r0 < M)     *(float2*)&C[(size_t)r0 * N2 + col]       = make_float2(v0, v1);
            if (r0 + 8 < M) *(float2*)&C[(size_t)(r0 + 8) * N2 + col] = make_float2(v2, v3);
        }
    }
}

// ================= launch (serial, R8 structure) =================
extern "C" void kernel_launch(void* const* d_in, const int* in_sizes, int n_in,
                              void* d_out, int out_size)
{
    const float* x   = (const float*)d_in[0];
    const int*   ei  = (const int*)d_in[1];
    const float* W1a = (const float*)d_in[2];
    const float* b1a = (const float*)d_in[3];
    const float* W2a = (const float*)d_in[4];
    const float* b2a = (const float*)d_in[5];
    const float* W1b = (const float*)d_in[6];
    const float* b1b = (const float*)d_in[7];
    const float* W2b = (const float*)d_in[8];
    const float* b2b = (const float*)d_in[9];
    float* out = (float*)d_out;

    __half *agg1, *agg2, *Wf1, *Wf2, *Wf3, *Wf4;
    float4 *h;
    int *cnt, *rowoff, *cursor, *csrsrc, *bsum;
    cudaGetSymbolAddress((void**)&agg1, g_agg1);
    cudaGetSymbolAddress((void**)&h,    g_h);
    cudaGetSymbolAddress((void**)&agg2, g_agg2);
    cudaGetSymbolAddress((void**)&Wf1,  g_Wf1);
    cudaGetSymbolAddress((void**)&Wf2,  g_Wf2);
    cudaGetSymbolAddress((void**)&Wf3,  g_Wf3);
    cudaGetSymbolAddress((void**)&Wf4,  g_Wf4);
    cudaGetSymbolAddress((void**)&cnt,    g_cnt);
    cudaGetSymbolAddress((void**)&rowoff, g_rowoff);
    cudaGetSymbolAddress((void**)&cursor, g_cursor);
    cudaGetSymbolAddress((void**)&csrsrc, g_csrsrc);
    cudaGetSymbolAddress((void**)&bsum,   g_bsum);

    const int* src = ei;
    const int* dst = ei + N_EDGES;

    const int mTiles = (N_NODES + 127) / 128;      // 782
    const int eBlocks = (N_EDGES + 255) / 256;
    const int nWarpBlocks = (N_NODES * 32 + 255) / 256;

    const int SM1 = (128 * 264 + 2 * 32 * HID_C) * 2;   // 100352 B
    const int SM2 = (128 * 264 + 2 * 32 * OUT_C) * 2;   //  83968 B
    cudaFuncSetAttribute(fused_mlp<IN_C,  HID_C, true >,
                         cudaFuncAttributeMaxDynamicSharedMemorySize, SM1);
    cudaFuncSetAttribute(fused_mlp<HID_C, OUT_C, false>,
                         cudaFuncAttributeMaxDynamicSharedMemorySize, SM2);

    // ---- CSR build (dst-sorted) ----
    cudaMemsetAsync(cnt, 0, N_NODES * sizeof(int));
    hist_kernel<<<eBlocks, 256>>>(dst, cnt);
    scan1_kernel<<<SCAN_NB, 1024>>>(cnt, rowoff, bsum);
    scan2_kernel<<<1, 128>>>(bsum);
    scan3_kernel<<<SCAN_NB, 1024>>>(rowoff, bsum, cursor);
    fill_kernel<<<eBlocks, 256>>>(src, dst, cursor, csrsrc);

    // ---- weight fragment packs (fp16) ----
    pack_kernel<IN_C,  HID_C><<<(IN_C * HID_C / 8 + 255) / 256, 256>>>(W1a, Wf1);
    pack_kernel<HID_C, HID_C><<<(HID_C * HID_C / 8 + 255) / 256, 256>>>(W2a, Wf2);
    pack_kernel<HID_C, HID_C><<<(HID_C * HID_C / 8 + 255) / 256, 256>>>(W1b, Wf3);
    pack_kernel<HID_C, OUT_C><<<(HID_C * OUT_C / 8 + 255) / 256, 256>>>(W2b, Wf4);

    // ---- conv1: reduce (fp16 out) + fused MLP ----
    csr_reduce_kernel<IN_C / 4><<<nWarpBlocks, 256>>>(
        (const float4*)x, rowoff, csrsrc, agg1);
    fused_mlp<IN_C, HID_C, true><<<mTiles, 512, SM1>>>(
        agg1, Wf1, b1a, Wf2, b2a, (float*)h);

    // ---- conv2: reduce (fp32 gather of h, fp16 out) + fused MLP ----
    csr_reduce_kernel<HID_C / 4><<<nWarpBlocks, 256>>>(
        (const float4*)h, rowoff, csrsrc, agg2);
    fused_mlp<HID_C, OUT_C, false><<<mTiles, 512, SM2>>>(
        agg2, Wf3, b1b, Wf4, b2b, out);
}

// round 13
// speedup vs baseline: 1.8038x; 1.1396x over previous
#include <cuda_runtime.h>
#include <cuda_fp16.h>
#include <cstdint>

#define N_NODES 100000
#define N_EDGES 1600000
#define IN_C 128
#define HID_C 256
#define OUT_C 128
#define SCAN_NB ((N_NODES + 1023) / 1024)   // 98

// ================= scratch =================
__device__ __half  g_agg1[N_NODES * IN_C];       // fp16 aggregated input (conv1)
__device__ __half  g_h   [N_NODES * HID_C];      // conv1 output (fp16, relu)
__device__ __half  g_agg2[N_NODES * HID_C];      // fp16 aggregated input (conv2)
__device__ __half  g_Wf1[IN_C * HID_C];          // fragment-packed fp16 weights
__device__ __half  g_Wf2[HID_C * HID_C];
__device__ __half  g_Wf3[HID_C * HID_C];
__device__ __half  g_Wf4[HID_C * OUT_C];
__device__ int     g_cnt[N_NODES];
__device__ int     g_rowoff[N_NODES + 1];
__device__ int     g_cursor[N_NODES];
__device__ int     g_csrsrc[N_EDGES];
__device__ int     g_bsum[SCAN_NB];

// ================= helpers =================
__device__ __forceinline__ uint32_t smem_u32(const void* p) {
    uint32_t a;
    asm("{ .reg .u64 t; cvta.to.shared.u64 t, %1; cvt.u32.u64 %0, t; }" : "=r"(a) : "l"(p));
    return a;
}
__device__ __forceinline__ void cp_async16(uint32_t dst, const void* src, bool pred) {
    int sz = pred ? 16 : 0;
    asm volatile("cp.async.ca.shared.global [%0], [%1], 16, %2;"
                 :: "r"(dst), "l"(src), "r"(sz) : "memory");
}
#define CP_COMMIT() asm volatile("cp.async.commit_group;" ::: "memory")
#define CP_WAIT(n)  asm volatile("cp.async.wait_group %0;" :: "n"(n) : "memory")

__device__ __forceinline__ void mma_f16(float* d, uint32_t a0, uint32_t a1,
                                        uint32_t a2, uint32_t a3,
                                        uint32_t b0, uint32_t b1) {
    asm volatile(
        "mma.sync.aligned.m16n8k16.row.col.f32.f16.f16.f32 "
        "{%0,%1,%2,%3}, {%4,%5,%6,%7}, {%8,%9}, {%0,%1,%2,%3};"
        : "+f"(d[0]), "+f"(d[1]), "+f"(d[2]), "+f"(d[3])
        : "r"(a0), "r"(a1), "r"(a2), "r"(a3), "r"(b0), "r"(b1));
}
__device__ __forceinline__ float4 f4add(float4 a, float4 b) {
    return make_float4(a.x + b.x, a.y + b.y, a.z + b.z, a.w + b.w);
}
__device__ __forceinline__ uint32_t pack_h2(float lo, float hi) {
    __half2 h = __floats2half2_rn(lo, hi);
    return *(uint32_t*)&h;
}
__device__ __forceinline__ void h8_add(float* acc, uint4 v) {
    float2 f;
    f = __half22float2(*(__half2*)&v.x); acc[0] += f.x; acc[1] += f.y;
    f = __half22float2(*(__half2*)&v.y); acc[2] += f.x; acc[3] += f.y;
    f = __half22float2(*(__half2*)&v.z); acc[4] += f.x; acc[5] += f.y;
    f = __half22float2(*(__half2*)&v.w); acc[6] += f.x; acc[7] += f.y;
}

// ================= weight fragment-pack (fp16) =================
template <int K, int NTOT>
__global__ void pack_kernel(const float* __restrict__ W, __half* __restrict__ Wf)
{
    constexpr int NT = NTOT / 64;
    constexpr int PER_G = 4 * NTOT;             // uint4s per 32-k chunk
    int id = blockIdx.x * 256 + threadIdx.x;
    if (id >= K * NTOT / 8) return;
    int q  = id % PER_G;
    int g  = id / PER_G;
    int lane = q & 31;
    int p    = (q >> 5) & 3;
    int rest = q >> 7;
    int wt   = rest % NT;
    int ks   = rest / NT;

    int gid = lane >> 2, tig = lane & 3;
    int n0 = wt * 64 + 2 * p * 8 + gid;
    int k0 = g * 32 + ks * 16 + tig * 2;

    uint4 v;
    v.x = pack_h2(W[(size_t)k0       * NTOT + n0],     W[(size_t)(k0 + 1) * NTOT + n0]);
    v.y = pack_h2(W[(size_t)(k0 + 8) * NTOT + n0],     W[(size_t)(k0 + 9) * NTOT + n0]);
    v.z = pack_h2(W[(size_t)k0       * NTOT + n0 + 8], W[(size_t)(k0 + 1) * NTOT + n0 + 8]);
    v.w = pack_h2(W[(size_t)(k0 + 8) * NTOT + n0 + 8], W[(size_t)(k0 + 9) * NTOT + n0 + 8]);
    *(uint4*)&Wf[(size_t)id * 8] = v;
}

// ================= CSR build =================
__global__ void hist_kernel(const int* __restrict__ dst, int* __restrict__ cnt)
{
    int e = blockIdx.x * 256 + threadIdx.x;
    if (e < N_EDGES) atomicAdd(&cnt[dst[e]], 1);
}

__global__ void scan1_kernel(const int* __restrict__ cnt, int* __restrict__ rowoff,
                             int* __restrict__ bsum)
{
    __shared__ int sh[1024];
    int tid = threadIdx.x;
    int i = blockIdx.x * 1024 + tid;
    int v = (i < N_NODES) ? cnt[i] : 0;
    sh[tid] = v;
    __syncthreads();
#pragma unroll
    for (int off = 1; off < 1024; off <<= 1) {
        int t = (tid >= off) ? sh[tid - off] : 0;
        __syncthreads();
        sh[tid] += t;
        __syncthreads();
    }
    if (i < N_NODES) rowoff[i] = sh[tid] - v;
    if (tid == 1023) bsum[blockIdx.x] = sh[tid];
}

__global__ void scan2_kernel(int* __restrict__ bsum)
{
    __shared__ int sh[128];
    int tid = threadIdx.x;
    int v = (tid < SCAN_NB) ? bsum[tid] : 0;
    sh[tid] = v;
    __syncthreads();
#pragma unroll
    for (int off = 1; off < 128; off <<= 1) {
        int t = (tid >= off) ? sh[tid - off] : 0;
        __syncthreads();
        sh[tid] += t;
        __syncthreads();
    }
    if (tid < SCAN_NB) bsum[tid] = sh[tid] - v;
}

__global__ void scan3_kernel(int* __restrict__ rowoff, const int* __restrict__ bsum,
                             int* __restrict__ cursor)
{
    int i = blockIdx.x * 1024 + threadIdx.x;
    if (i < N_NODES) {
        int r = rowoff[i] + bsum[blockIdx.x];
        rowoff[i] = r;
        cursor[i] = r;
    }
    if (i == 0) rowoff[N_NODES] = N_EDGES;
}

__global__ void fill_kernel(const int* __restrict__ src, const int* __restrict__ dst,
                            int* __restrict__ cursor, int* __restrict__ csrsrc)
{
    int e = blockIdx.x * 256 + threadIdx.x;
    if (e >= N_EDGES) return;
    int pos = atomicAdd(&cursor[dst[e]], 1);
    csrsrc[pos] = src[e];
}

// ================= CSR gather-reduce (fp32 source) =================
template <int V>   // V = channels/4
__global__ void __launch_bounds__(256) csr_reduce_kernel(
    const float4* __restrict__ x,
    const int* __restrict__ rowoff,
    const int* __restrict__ csrsrc,
    __half* __restrict__ agg)
{
    constexpr int J = V / 32;
    constexpr int C = V * 4;
    int node = (int)((blockIdx.x * 256u + threadIdx.x) >> 5);
    if (node >= N_NODES) return;
    int lane = threadIdx.x & 31;

    float4 acc[J];
#pragma unroll
    for (int j = 0; j < J; j++)
        acc[j] = x[(size_t)node * V + j * 32 + lane];

    int b = __ldg(&rowoff[node]);
    int e = __ldg(&rowoff[node + 1]);
    for (; b + 1 < e; b += 2) {
        int s0 = __ldg(&csrsrc[b]);
        int s1 = __ldg(&csrsrc[b + 1]);
#pragma unroll
        for (int j = 0; j < J; j++) {
            float4 v0 = x[(size_t)s0 * V + j * 32 + lane];
            float4 v1 = x[(size_t)s1 * V + j * 32 + lane];
            acc[j] = f4add(acc[j], f4add(v0, v1));
        }
    }
    if (b < e) {
        int s0 = __ldg(&csrsrc[b]);
#pragma unroll
        for (int j = 0; j < J; j++)
            acc[j] = f4add(acc[j], x[(size_t)s0 * V + j * 32 + lane]);
    }
#pragma unroll
    for (int j = 0; j < J; j++) {
        uint2 u;
        u.x = pack_h2(acc[j].x, acc[j].y);
        u.y = pack_h2(acc[j].z, acc[j].w);
        *(uint2*)&agg[(size_t)node * C + (j * 32 + lane) * 4] = u;
    }
}

// ================= CSR gather-reduce (fp16 source, 256ch) =================
// lane handles 8 halves (one uint4); warp covers the 256-ch row exactly
__global__ void __launch_bounds__(256) csr_reduce_h16(
    const uint4* __restrict__ x,        // [N_NODES * 32] (each uint4 = 8 halves)
    const int* __restrict__ rowoff,
    const int* __restrict__ csrsrc,
    __half* __restrict__ agg)           // [N_NODES * 256]
{
    int node = (int)((blockIdx.x * 256u + threadIdx.x) >> 5);
    if (node >= N_NODES) return;
    int lane = threadIdx.x & 31;

    float acc[8] = {0, 0, 0, 0, 0, 0, 0, 0};
    h8_add(acc, x[(size_t)node * 32 + lane]);       // self term

    int b = __ldg(&rowoff[node]);
    int e = __ldg(&rowoff[node + 1]);
    for (; b + 1 < e; b += 2) {
        int s0 = __ldg(&csrsrc[b]);
        int s1 = __ldg(&csrsrc[b + 1]);
        uint4 v0 = x[(size_t)s0 * 32 + lane];
        uint4 v1 = x[(size_t)s1 * 32 + lane];
        h8_add(acc, v0);
        h8_add(acc, v1);
    }
    if (b < e)
        h8_add(acc, x[(size_t)__ldg(&csrsrc[b]) * 32 + lane]);

    uint4 o;
    o.x = pack_h2(acc[0], acc[1]);
    o.y = pack_h2(acc[2], acc[3]);
    o.z = pack_h2(acc[4], acc[5]);
    o.w = pack_h2(acc[6], acc[7]);
    *(uint4*)&agg[(size_t)node * 256 + lane * 8] = o;
}

// ================= fused 2-layer MLP, fp16 MMA =================
template <int K, int N2, bool OUTER_RELU, bool HALF_OUT>
__global__ void __launch_bounds__(512) fused_mlp(
    const __half* __restrict__ A,      // [M, K] fp16
    const __half* __restrict__ Wp1,    // packed fp16 [K x 256]
    const float* __restrict__ b1v,
    const __half* __restrict__ Wp2,    // packed fp16 [256 x N2]
    const float* __restrict__ b2v,
    void* __restrict__ Cv)
{
    constexpr int BM = 128;
    constexpr int GA = K / 32, GB = HID_C / 32;
    constexpr int NT2 = N2 / 64;
    constexpr int NF  = N2 / 32;
    constexpr int NPL = NF / 2;
    constexpr int M = N_NODES;
    constexpr int AP = 40, HP = 264;
    constexpr int ABUF  = BM * AP;
    constexpr int W1OFF = 2 * ABUF;
    constexpr int WBUF1 = 8192;
    constexpr int W2OFF = BM * HP;
    constexpr int WBUF2 = 32 * N2;

    extern __shared__ __half smh[];
    const uint32_t sbase = smem_u32(smh);

    const int tid  = threadIdx.x;
    const int wid  = tid >> 5;
    const int lane = tid & 31;
    const int gid  = lane >> 2;
    const int tig  = lane & 3;
    const int wm   = wid & 3;
    const int wn   = wid >> 2;
    const int rA   = wm * 32;
    const int m0   = blockIdx.x * BM;

    float acc[2][8][4];
#pragma unroll
    for (int i = 0; i < 2; i++)
#pragma unroll
        for (int j = 0; j < 8; j++)
#pragma unroll
            for (int c = 0; c < 4; c++) acc[i][j][c] = 0.0f;

    auto loadA = [&](int g) {
        const int s = g & 1;
        {
            int row = tid >> 2, c4 = tid & 3;
            cp_async16(sbase + (uint32_t)(s * ABUF + row * AP + c4 * 8) * 2u,
                       A + (size_t)(m0 + row) * K + g * 32 + c4 * 8,
                       (m0 + row) < M);
        }
#pragma unroll
        for (int j = 0; j < 2; j++) {
            int idx = j * 512 + tid;
            cp_async16(sbase + (uint32_t)(W1OFF + s * WBUF1 + idx * 8) * 2u,
                       Wp1 + (size_t)g * WBUF1 + idx * 8, true);
        }
        CP_COMMIT();
    };
    auto loadB = [&](int g) {
        const int s = g & 1;
#pragma unroll
        for (int j = 0; j < WBUF2 / 8 / 512; j++) {
            int idx = j * 512 + tid;
            cp_async16(sbase + (uint32_t)(W2OFF + s * WBUF2 + idx * 8) * 2u,
                       Wp2 + (size_t)g * WBUF2 + idx * 8, true);
        }
        CP_COMMIT();
    };

    // ---- phase A: Hacc = A @ W1 ----
    loadA(0);
    for (int g = 0; g < GA; g++) {
        if (g + 1 < GA) { loadA(g + 1); CP_WAIT(1); }
        else            { CP_WAIT(0); }
        __syncthreads();
        const __half* ah = smh + (g & 1) * ABUF;
        const float4* bf = (const float4*)(smh + W1OFF + (g & 1) * WBUF1);
#pragma unroll
        for (int ks = 0; ks < 2; ks++) {
            const int k0 = ks * 16 + 2 * tig;
            uint32_t a[2][4];
#pragma unroll
            for (int mf = 0; mf < 2; mf++) {
                int base = rA + mf * 16;
                a[mf][0] = *(const uint32_t*)&ah[(base + gid)     * AP + k0];
                a[mf][1] = *(const uint32_t*)&ah[(base + gid + 8) * AP + k0];
                a[mf][2] = *(const uint32_t*)&ah[(base + gid)     * AP + k0 + 8];
                a[mf][3] = *(const uint32_t*)&ah[(base + gid + 8) * AP + k0 + 8];
            }
            uint32_t b[8][2];
#pragma unroll
            for (int p = 0; p < 4; p++) {
                float4 q = bf[((ks * 4 + wn) * 4 + p) * 32 + lane];
                b[2 * p][0]     = __float_as_uint(q.x);
                b[2 * p][1]     = __float_as_uint(q.y);
                b[2 * p + 1][0] = __float_as_uint(q.z);
                b[2 * p + 1][1] = __float_as_uint(q.w);
            }
#pragma unroll
            for (int mf = 0; mf < 2; mf++)
#pragma unroll
                for (int nf = 0; nf < 8; nf++)
                    mma_f16(acc[mf][nf], a[mf][0], a[mf][1], a[mf][2], a[mf][3],
                            b[nf][0], b[nf][1]);
        }
        __syncthreads();
    }

    loadB(0);

    // ---- spill H = fp16(relu(acc + b1)) into smem ----
#pragma unroll
    for (int nf = 0; nf < 8; nf++) {
        int col = wn * 64 + nf * 8 + tig * 2;
        float c0 = b1v[col], c1 = b1v[col + 1];
#pragma unroll
        for (int mf = 0; mf < 2; mf++) {
            int r0 = rA + mf * 16 + gid;
            *(uint32_t*)&smh[(size_t)r0 * HP + col] =
                pack_h2(fmaxf(acc[mf][nf][0] + c0, 0.f), fmaxf(acc[mf][nf][1] + c1, 0.f));
            *(uint32_t*)&smh[(size_t)(r0 + 8) * HP + col] =
                pack_h2(fmaxf(acc[mf][nf][2] + c0, 0.f), fmaxf(acc[mf][nf][3] + c1, 0.f));
        }
    }
#pragma unroll
    for (int i = 0; i < 2; i++)
#pragma unroll
        for (int j = 0; j < 8; j++)
#pragma unroll
            for (int c = 0; c < 4; c++) acc[i][j][c] = 0.0f;

    // ---- phase 4: OUT = H @ W2 ----
    const int grp = (NF == 8) ? wn : (wn >> 1);
    for (int g = 0; g < GB; g++) {
        if (g + 1 < GB) { loadB(g + 1); CP_WAIT(1); }
        else            { CP_WAIT(0); }
        __syncthreads();
        const float4* bf = (const float4*)(smh + W2OFF + (g & 1) * WBUF2);
#pragma unroll
        for (int ks = 0; ks < 2; ks++) {
            const int k0 = g * 32 + ks * 16 + 2 * tig;
            uint32_t a[2][4];
#pragma unroll
            for (int mf = 0; mf < 2; mf++) {
                int base = rA + mf * 16;
                a[mf][0] = *(const uint32_t*)&smh[(size_t)(base + gid)     * HP + k0];
                a[mf][1] = *(const uint32_t*)&smh[(size_t)(base + gid + 8) * HP + k0];
                a[mf][2] = *(const uint32_t*)&smh[(size_t)(base + gid)     * HP + k0 + 8];
                a[mf][3] = *(const uint32_t*)&smh[(size_t)(base + gid + 8) * HP + k0 + 8];
            }
            uint32_t b[8][2];
#pragma unroll
            for (int pl = 0; pl < NPL; pl++) {
                int p = (NF == 8) ? pl : (2 * (wn & 1) + pl);
                float4 q = bf[((ks * NT2 + grp) * 4 + p) * 32 + lane];
                b[2 * pl][0]     = __float_as_uint(q.x);
                b[2 * pl][1]     = __float_as_uint(q.y);
                b[2 * pl + 1][0] = __float_as_uint(q.z);
                b[2 * pl + 1][1] = __float_as_uint(q.w);
            }
#pragma unroll
            for (int mf = 0; mf < 2; mf++)
#pragma unroll
                for (int nf = 0; nf < NF; nf++)
                    mma_f16(acc[mf][nf], a[mf][0], a[mf][1], a[mf][2], a[mf][3],
                            b[nf][0], b[nf][1]);
        }
        __syncthreads();
    }

    // ---- epilogue ----
#pragma unroll
    for (int nf = 0; nf < NF; nf++) {
        int col = wn * (N2 / 4) + nf * 8 + tig * 2;
        float c0 = b2v[col], c1 = b2v[col + 1];
#pragma unroll
        for (int mf = 0; mf < 2; mf++) {
            int r0 = m0 + rA + mf * 16 + gid;
            float v0 = acc[mf][nf][0] + c0, v1 = acc[mf][nf][1] + c1;
            float v2 = acc[mf][nf][2] + c0, v3 = acc[mf][nf][3] + c1;
            if (OUTER_RELU) {
                v0 = fmaxf(v0, 0.f); v1 = fmaxf(v1, 0.f);
                v2 = fmaxf(v2, 0.f); v3 = fmaxf(v3, 0.f);
            }
            if (HALF_OUT) {
                __half* Ch = (__half*)Cv;
                if (r0 < M)
                    *(uint32_t*)&Ch[(size_t)r0 * N2 + col] = pack_h2(v0, v1);
                if (r0 + 8 < M)
                    *(uint32_t*)&Ch[(size_t)(r0 + 8) * N2 + col] = pack_h2(v2, v3);
            } else {
                float* Cf = (float*)Cv;
                if (r0 < M)
                    *(float2*)&Cf[(size_t)r0 * N2 + col] = make_float2(v0, v1);
                if (r0 + 8 < M)
                    *(float2*)&Cf[(size_t)(r0 + 8) * N2 + col] = make_float2(v2, v3);
            }
        }
    }
}

// ================= launch =================
extern "C" void kernel_launch(void* const* d_in, const int* in_sizes, int n_in,
                              void* d_out, int out_size)
{
    const float* x   = (const float*)d_in[0];
    const int*   ei  = (const int*)d_in[1];
    const float* W1a = (const float*)d_in[2];
    const float* b1a = (const float*)d_in[3];
    const float* W2a = (const float*)d_in[4];
    const float* b2a = (const float*)d_in[5];
    const float* W1b = (const float*)d_in[6];
    const float* b1b = (const float*)d_in[7];
    const float* W2b = (const float*)d_in[8];
    const float* b2b = (const float*)d_in[9];
    float* out = (float*)d_out;

    __half *agg1, *h, *agg2, *Wf1, *Wf2, *Wf3, *Wf4;
    int *cnt, *rowoff, *cursor, *csrsrc, *bsum;
    cudaGetSymbolAddress((void**)&agg1, g_agg1);
    cudaGetSymbolAddress((void**)&h,    g_h);
    cudaGetSymbolAddress((void**)&agg2, g_agg2);
    cudaGetSymbolAddress((void**)&Wf1,  g_Wf1);
    cudaGetSymbolAddress((void**)&Wf2,  g_Wf2);
    cudaGetSymbolAddress((void**)&Wf3,  g_Wf3);
    cudaGetSymbolAddress((void**)&Wf4,  g_Wf4);
    cudaGetSymbolAddress((void**)&cnt,    g_cnt);
    cudaGetSymbolAddress((void**)&rowoff, g_rowoff);
    cudaGetSymbolAddress((void**)&cursor, g_cursor);
    cudaGetSymbolAddress((void**)&csrsrc, g_csrsrc);
    cudaGetSymbolAddress((void**)&bsum,   g_bsum);

    const int* src = ei;
    const int* dst = ei + N_EDGES;

    const int mTiles = (N_NODES + 127) / 128;      // 782
    const int eBlocks = (N_EDGES + 255) / 256;
    const int nWarpBlocks = (N_NODES * 32 + 255) / 256;

    const int SM1 = (128 * 264 + 2 * 32 * HID_C) * 2;   // 100352 B
    const int SM2 = (128 * 264 + 2 * 32 * OUT_C) * 2;   //  83968 B
    cudaFuncSetAttribute(fused_mlp<IN_C,  HID_C, true,  true >,
                         cudaFuncAttributeMaxDynamicSharedMemorySize, SM1);
    cudaFuncSetAttribute(fused_mlp<HID_C, OUT_C, false, false>,
                         cudaFuncAttributeMaxDynamicSharedMemorySize, SM2);

    // ---- CSR build (dst-sorted) ----
    cudaMemsetAsync(cnt, 0, N_NODES * sizeof(int));
    hist_kernel<<<eBlocks, 256>>>(dst, cnt);
    scan1_kernel<<<SCAN_NB, 1024>>>(cnt, rowoff, bsum);
    scan2_kernel<<<1, 128>>>(bsum);
    scan3_kernel<<<SCAN_NB, 1024>>>(rowoff, bsum, cursor);
    fill_kernel<<<eBlocks, 256>>>(src, dst, cursor, csrsrc);

    // ---- weight fragment packs (fp16) ----
    pack_kernel<IN_C,  HID_C><<<(IN_C * HID_C / 8 + 255) / 256, 256>>>(W1a, Wf1);
    pack_kernel<HID_C, HID_C><<<(HID_C * HID_C / 8 + 255) / 256, 256>>>(W2a, Wf2);
    pack_kernel<HID_C, HID_C><<<(HID_C * HID_C / 8 + 255) / 256, 256>>>(W1b, Wf3);
    pack_kernel<HID_C, OUT_C><<<(HID_C * OUT_C / 8 + 255) / 256, 256>>>(W2b, Wf4);

    // ---- conv1: reduce (fp32 x -> fp16 agg) + fused MLP (fp16 h out) ----
    csr_reduce_kernel<IN_C / 4><<<nWarpBlocks, 256>>>(
        (const float4*)x, rowoff, csrsrc, agg1);
    fused_mlp<IN_C, HID_C, true, true><<<mTiles, 512, SM1>>>(
        agg1, Wf1, b1a, Wf2, b2a, h);

    // ---- conv2: reduce (fp16 h -> fp16 agg) + fused MLP (fp32 out) ----
    csr_reduce_h16<<<nWarpBlocks, 256>>>(
        (const uint4*)h, rowoff, csrsrc, agg2);
    fused_mlp<HID_C, OUT_C, false, false><<<mTiles, 512, SM2>>>(
        agg2, Wf3, b1b, Wf4, b2b, out);
}

// round 14
// speedup vs baseline: 1.8071x; 1.0019x over previous
#include <cuda_runtime.h>
#include <cuda_fp16.h>
#include <cstdint>

#define N_NODES 100000
#define N_EDGES 1600000
#define IN_C 128
#define HID_C 256
#define OUT_C 128
#define SCAN_NB ((N_NODES + 1023) / 1024)   // 98

// ================= scratch =================
__device__ __half  g_xh  [N_NODES * IN_C];       // fp16 copy of x
__device__ __half  g_agg1[N_NODES * IN_C];       // fp16 aggregated input (conv1)
__device__ __half  g_h   [N_NODES * HID_C];      // conv1 output (fp16, relu)
__device__ __half  g_agg2[N_NODES * HID_C];      // fp16 aggregated input (conv2)
__device__ __half  g_Wf1[IN_C * HID_C];          // fragment-packed fp16 weights
__device__ __half  g_Wf2[HID_C * HID_C];
__device__ __half  g_Wf3[HID_C * HID_C];
__device__ __half  g_Wf4[HID_C * OUT_C];
__device__ int     g_cnt[N_NODES];
__device__ int     g_rowoff[N_NODES + 1];
__device__ int     g_cursor[N_NODES];
__device__ int     g_csrsrc[N_EDGES];
__device__ int     g_bsum[SCAN_NB];

// ================= helpers =================
__device__ __forceinline__ uint32_t smem_u32(const void* p) {
    uint32_t a;
    asm("{ .reg .u64 t; cvta.to.shared.u64 t, %1; cvt.u32.u64 %0, t; }" : "=r"(a) : "l"(p));
    return a;
}
__device__ __forceinline__ void cp_async16(uint32_t dst, const void* src, bool pred) {
    int sz = pred ? 16 : 0;
    asm volatile("cp.async.ca.shared.global [%0], [%1], 16, %2;"
                 :: "r"(dst), "l"(src), "r"(sz) : "memory");
}
#define CP_COMMIT() asm volatile("cp.async.commit_group;" ::: "memory")
#define CP_WAIT(n)  asm volatile("cp.async.wait_group %0;" :: "n"(n) : "memory")

__device__ __forceinline__ void mma_f16(float* d, uint32_t a0, uint32_t a1,
                                        uint32_t a2, uint32_t a3,
                                        uint32_t b0, uint32_t b1) {
    asm volatile(
        "mma.sync.aligned.m16n8k16.row.col.f32.f16.f16.f32 "
        "{%0,%1,%2,%3}, {%4,%5,%6,%7}, {%8,%9}, {%0,%1,%2,%3};"
        : "+f"(d[0]), "+f"(d[1]), "+f"(d[2]), "+f"(d[3])
        : "r"(a0), "r"(a1), "r"(a2), "r"(a3), "r"(b0), "r"(b1));
}
__device__ __forceinline__ uint32_t pack_h2(float lo, float hi) {
    __half2 h = __floats2half2_rn(lo, hi);
    return *(uint32_t*)&h;
}
__device__ __forceinline__ void h8_add(float* acc, uint4 v) {
    float2 f;
    f = __half22float2(*(__half2*)&v.x); acc[0] += f.x; acc[1] += f.y;
    f = __half22float2(*(__half2*)&v.y); acc[2] += f.x; acc[3] += f.y;
    f = __half22float2(*(__half2*)&v.z); acc[4] += f.x; acc[5] += f.y;
    f = __half22float2(*(__half2*)&v.w); acc[6] += f.x; acc[7] += f.y;
}
__device__ __forceinline__ void h4_add(float* acc, uint2 v) {
    float2 f;
    f = __half22float2(*(__half2*)&v.x); acc[0] += f.x; acc[1] += f.y;
    f = __half22float2(*(__half2*)&v.y); acc[2] += f.x; acc[3] += f.y;
}

// ================= x -> fp16 convert =================
__global__ void convert_kernel(const float4* __restrict__ x, uint4* __restrict__ xh, int n8)
{
    int i = blockIdx.x * 256 + threadIdx.x;
    if (i >= n8) return;
    float4 a = x[2 * i], b = x[2 * i + 1];
    uint4 o;
    o.x = pack_h2(a.x, a.y);
    o.y = pack_h2(a.z, a.w);
    o.z = pack_h2(b.x, b.y);
    o.w = pack_h2(b.z, b.w);
    xh[i] = o;
}

// ================= weight fragment-pack (fp16) =================
template <int K, int NTOT>
__global__ void pack_kernel(const float* __restrict__ W, __half* __restrict__ Wf)
{
    constexpr int NT = NTOT / 64;
    constexpr int PER_G = 4 * NTOT;             // uint4s per 32-k chunk
    int id = blockIdx.x * 256 + threadIdx.x;
    if (id >= K * NTOT / 8) return;
    int q  = id % PER_G;
    int g  = id / PER_G;
    int lane = q & 31;
    int p    = (q >> 5) & 3;
    int rest = q >> 7;
    int wt   = rest % NT;
    int ks   = rest / NT;

    int gid = lane >> 2, tig = lane & 3;
    int n0 = wt * 64 + 2 * p * 8 + gid;
    int k0 = g * 32 + ks * 16 + tig * 2;

    uint4 v;
    v.x = pack_h2(W[(size_t)k0       * NTOT + n0],     W[(size_t)(k0 + 1) * NTOT + n0]);
    v.y = pack_h2(W[(size_t)(k0 + 8) * NTOT + n0],     W[(size_t)(k0 + 9) * NTOT + n0]);
    v.z = pack_h2(W[(size_t)k0       * NTOT + n0 + 8], W[(size_t)(k0 + 1) * NTOT + n0 + 8]);
    v.w = pack_h2(W[(size_t)(k0 + 8) * NTOT + n0 + 8], W[(size_t)(k0 + 9) * NTOT + n0 + 8]);
    *(uint4*)&Wf[(size_t)id * 8] = v;
}

// ================= CSR build =================
__global__ void hist_kernel(const int* __restrict__ dst, int* __restrict__ cnt)
{
    int e = blockIdx.x * 256 + threadIdx.x;
    if (e < N_EDGES) atomicAdd(&cnt[dst[e]], 1);
}

__global__ void scan1_kernel(const int* __restrict__ cnt, int* __restrict__ rowoff,
                             int* __restrict__ bsum)
{
    __shared__ int sh[1024];
    int tid = threadIdx.x;
    int i = blockIdx.x * 1024 + tid;
    int v = (i < N_NODES) ? cnt[i] : 0;
    sh[tid] = v;
    __syncthreads();
#pragma unroll
    for (int off = 1; off < 1024; off <<= 1) {
        int t = (tid >= off) ? sh[tid - off] : 0;
        __syncthreads();
        sh[tid] += t;
        __syncthreads();
    }
    if (i < N_NODES) rowoff[i] = sh[tid] - v;
    if (tid == 1023) bsum[blockIdx.x] = sh[tid];
}

__global__ void scan2_kernel(int* __restrict__ bsum)
{
    __shared__ int sh[128];
    int tid = threadIdx.x;
    int v = (tid < SCAN_NB) ? bsum[tid] : 0;
    sh[tid] = v;
    __syncthreads();
#pragma unroll
    for (int off = 1; off < 128; off <<= 1) {
        int t = (tid >= off) ? sh[tid - off] : 0;
        __syncthreads();
        sh[tid] += t;
        __syncthreads();
    }
    if (tid < SCAN_NB) bsum[tid] = sh[tid] - v;
}

__global__ void scan3_kernel(int* __restrict__ rowoff, const int* __restrict__ bsum,
                             int* __restrict__ cursor)
{
    int i = blockIdx.x * 1024 + threadIdx.x;
    if (i < N_NODES) {
        int r = rowoff[i] + bsum[blockIdx.x];
        rowoff[i] = r;
        cursor[i] = r;
    }
    if (i == 0) rowoff[N_NODES] = N_EDGES;
}

__global__ void fill_kernel(const int* __restrict__ src, const int* __restrict__ dst,
                            int* __restrict__ cursor, int* __restrict__ csrsrc)
{
    int e = blockIdx.x * 256 + threadIdx.x;
    if (e >= N_EDGES) return;
    int pos = atomicAdd(&cursor[dst[e]], 1);
    csrsrc[pos] = src[e];
}

// ================= CSR gather-reduce, fp16 source, 128ch =================
__global__ void __launch_bounds__(256) csr_reduce_h16_128(
    const uint2* __restrict__ x,        // [N_NODES * 32] (each uint2 = 4 halves)
    const int* __restrict__ rowoff,
    const int* __restrict__ csrsrc,
    __half* __restrict__ agg)           // [N_NODES * 128]
{
    int node = (int)((blockIdx.x * 256u + threadIdx.x) >> 5);
    if (node >= N_NODES) return;
    int lane = threadIdx.x & 31;

    float acc[4] = {0, 0, 0, 0};
    h4_add(acc, x[(size_t)node * 32 + lane]);       // self term

    int b = __ldg(&rowoff[node]);
    int e = __ldg(&rowoff[node + 1]);
    for (; b + 1 < e; b += 2) {
        int s0 = __ldg(&csrsrc[b]);
        int s1 = __ldg(&csrsrc[b + 1]);
        uint2 v0 = x[(size_t)s0 * 32 + lane];
        uint2 v1 = x[(size_t)s1 * 32 + lane];
        h4_add(acc, v0);
        h4_add(acc, v1);
    }
    if (b < e)
        h4_add(acc, x[(size_t)__ldg(&csrsrc[b]) * 32 + lane]);

    uint2 o;
    o.x = pack_h2(acc[0], acc[1]);
    o.y = pack_h2(acc[2], acc[3]);
    *(uint2*)&agg[(size_t)node * 128 + lane * 4] = o;
}

// ================= CSR gather-reduce, fp16 source, 256ch =================
__global__ void __launch_bounds__(256) csr_reduce_h16_256(
    const uint4* __restrict__ x,        // [N_NODES * 32] (each uint4 = 8 halves)
    const int* __restrict__ rowoff,
    const int* __restrict__ csrsrc,
    __half* __restrict__ agg)           // [N_NODES * 256]
{
    int node = (int)((blockIdx.x * 256u + threadIdx.x) >> 5);
    if (node >= N_NODES) return;
    int lane = threadIdx.x & 31;

    float acc[8] = {0, 0, 0, 0, 0, 0, 0, 0};
    h8_add(acc, x[(size_t)node * 32 + lane]);       // self term

    int b = __ldg(&rowoff[node]);
    int e = __ldg(&rowoff[node + 1]);
    for (; b + 1 < e; b += 2) {
        int s0 = __ldg(&csrsrc[b]);
        int s1 = __ldg(&csrsrc[b + 1]);
        uint4 v0 = x[(size_t)s0 * 32 + lane];
        uint4 v1 = x[(size_t)s1 * 32 + lane];
        h8_add(acc, v0);
        h8_add(acc, v1);
    }
    if (b < e)
        h8_add(acc, x[(size_t)__ldg(&csrsrc[b]) * 32 + lane]);

    uint4 o;
    o.x = pack_h2(acc[0], acc[1]);
    o.y = pack_h2(acc[2], acc[3]);
    o.z = pack_h2(acc[4], acc[5]);
    o.w = pack_h2(acc[6], acc[7]);
    *(uint4*)&agg[(size_t)node * 256 + lane * 8] = o;
}

// ================= fused 2-layer MLP, fp16 MMA =================
template <int K, int N2, bool OUTER_RELU, bool HALF_OUT>
__global__ void __launch_bounds__(512) fused_mlp(
    const __half* __restrict__ A,      // [M, K] fp16
    const __half* __restrict__ Wp1,    // packed fp16 [K x 256]
    const float* __restrict__ b1v,
    const __half* __restrict__ Wp2,    // packed fp16 [256 x N2]
    const float* __restrict__ b2v,
    void* __restrict__ Cv)
{
    constexpr int BM = 128;
    constexpr int GA = K / 32, GB = HID_C / 32;
    constexpr int NT2 = N2 / 64;
    constexpr int NF  = N2 / 32;
    constexpr int NPL = NF / 2;
    constexpr int M = N_NODES;
    constexpr int AP = 40, HP = 264;
    constexpr int ABUF  = BM * AP;
    constexpr int W1OFF = 2 * ABUF;
    constexpr int WBUF1 = 8192;
    constexpr int W2OFF = BM * HP;
    constexpr int WBUF2 = 32 * N2;

    extern __shared__ __half smh[];
    const uint32_t sbase = smem_u32(smh);

    const int tid  = threadIdx.x;
    const int wid  = tid >> 5;
    const int lane = tid & 31;
    const int gid  = lane >> 2;
    const int tig  = lane & 3;
    const int wm   = wid & 3;
    const int wn   = wid >> 2;
    const int rA   = wm * 32;
    const int m0   = blockIdx.x * BM;

    float acc[2][8][4];
#pragma unroll
    for (int i = 0; i < 2; i++)
#pragma unroll
        for (int j = 0; j < 8; j++)
#pragma unroll
            for (int c = 0; c < 4; c++) acc[i][j][c] = 0.0f;

    auto loadA = [&](int g) {
        const int s = g & 1;
        {
            int row = tid >> 2, c4 = tid & 3;
            cp_async16(sbase + (uint32_t)(s * ABUF + row * AP + c4 * 8) * 2u,
                       A + (size_t)(m0 + row) * K + g * 32 + c4 * 8,
                       (m0 + row) < M);
        }
#pragma unroll
        for (int j = 0; j < 2; j++) {
            int idx = j * 512 + tid;
            cp_async16(sbase + (uint32_t)(W1OFF + s * WBUF1 + idx * 8) * 2u,
                       Wp1 + (size_t)g * WBUF1 + idx * 8, true);
        }
        CP_COMMIT();
    };
    auto loadB = [&](int g) {
        const int s = g & 1;
#pragma unroll
        for (int j = 0; j < WBUF2 / 8 / 512; j++) {
            int idx = j * 512 + tid;
            cp_async16(sbase + (uint32_t)(W2OFF + s * WBUF2 + idx * 8) * 2u,
                       Wp2 + (size_t)g * WBUF2 + idx * 8, true);
        }
        CP_COMMIT();
    };

    // ---- phase A: Hacc = A @ W1 ----
    loadA(0);
    for (int g = 0; g < GA; g++) {
        if (g + 1 < GA) { loadA(g + 1); CP_WAIT(1); }
        else            { CP_WAIT(0); }
        __syncthreads();
        const __half* ah = smh + (g & 1) * ABUF;
        const float4* bf = (const float4*)(smh + W1OFF + (g & 1) * WBUF1);
#pragma unroll
        for (int ks = 0; ks < 2; ks++) {
            const int k0 = ks * 16 + 2 * tig;
            uint32_t a[2][4];
#pragma unroll
            for (int mf = 0; mf < 2; mf++) {
                int base = rA + mf * 16;
                a[mf][0] = *(const uint32_t*)&ah[(base + gid)     * AP + k0];
                a[mf][1] = *(const uint32_t*)&ah[(base + gid + 8) * AP + k0];
                a[mf][2] = *(const uint32_t*)&ah[(base + gid)     * AP + k0 + 8];
                a[mf][3] = *(const uint32_t*)&ah[(base + gid + 8) * AP + k0 + 8];
            }
            uint32_t b[8][2];
#pragma unroll
            for (int p = 0; p < 4; p++) {
                float4 q = bf[((ks * 4 + wn) * 4 + p) * 32 + lane];
                b[2 * p][0]     = __float_as_uint(q.x);
                b[2 * p][1]     = __float_as_uint(q.y);
                b[2 * p + 1][0] = __float_as_uint(q.z);
                b[2 * p + 1][1] = __float_as_uint(q.w);
            }
#pragma unroll
            for (int mf = 0; mf < 2; mf++)
#pragma unroll
                for (int nf = 0; nf < 8; nf++)
                    mma_f16(acc[mf][nf], a[mf][0], a[mf][1], a[mf][2], a[mf][3],
                            b[nf][0], b[nf][1]);
        }
        __syncthreads();
    }

    loadB(0);

    // ---- spill H = fp16(relu(acc + b1)) into smem ----
#pragma unroll
    for (int nf = 0; nf < 8; nf++) {
        int col = wn * 64 + nf * 8 + tig * 2;
        float c0 = b1v[col], c1 = b1v[col + 1];
#pragma unroll
        for (int mf = 0; mf < 2; mf++) {
            int r0 = rA + mf * 16 + gid;
            *(uint32_t*)&smh[(size_t)r0 * HP + col] =
                pack_h2(fmaxf(acc[mf][nf][0] + c0, 0.f), fmaxf(acc[mf][nf][1] + c1, 0.f));
            *(uint32_t*)&smh[(size_t)(r0 + 8) * HP + col] =
                pack_h2(fmaxf(acc[mf][nf][2] + c0, 0.f), fmaxf(acc[mf][nf][3] + c1, 0.f));
        }
    }
#pragma unroll
    for (int i = 0; i < 2; i++)
#pragma unroll
        for (int j = 0; j < 8; j++)
#pragma unroll
            for (int c = 0; c < 4; c++) acc[i][j][c] = 0.0f;

    // ---- phase 4: OUT = H @ W2 ----
    const int grp = (NF == 8) ? wn : (wn >> 1);
    for (int g = 0; g < GB; g++) {
        if (g + 1 < GB) { loadB(g + 1); CP_WAIT(1); }
        else            { CP_WAIT(0); }
        __syncthreads();
        const float4* bf = (const float4*)(smh + W2OFF + (g & 1) * WBUF2);
#pragma unroll
        for (int ks = 0; ks < 2; ks++) {
            const int k0 = g * 32 + ks * 16 + 2 * tig;
            uint32_t a[2][4];
#pragma unroll
            for (int mf = 0; mf < 2; mf++) {
                int base = rA + mf * 16;
                a[mf][0] = *(const uint32_t*)&smh[(size_t)(base + gid)     * HP + k0];
                a[mf][1] = *(const uint32_t*)&smh[(size_t)(base + gid + 8) * HP + k0];
                a[mf][2] = *(const uint32_t*)&smh[(size_t)(base + gid)     * HP + k0 + 8];
                a[mf][3] = *(const uint32_t*)&smh[(size_t)(base + gid + 8) * HP + k0 + 8];
            }
            uint32_t b[8][2];
#pragma unroll
            for (int pl = 0; pl < NPL; pl++) {
                int p = (NF == 8) ? pl : (2 * (wn & 1) + pl);
                float4 q = bf[((ks * NT2 + grp) * 4 + p) * 32 + lane];
                b[2 * pl][0]     = __float_as_uint(q.x);
                b[2 * pl][1]     = __float_as_uint(q.y);
                b[2 * pl + 1][0] = __float_as_uint(q.z);
                b[2 * pl + 1][1] = __float_as_uint(q.w);
            }
#pragma unroll
            for (int mf = 0; mf < 2; mf++)
#pragma unroll
                for (int nf = 0; nf < NF; nf++)
                    mma_f16(acc[mf][nf], a[mf][0], a[mf][1], a[mf][2], a[mf][3],
                            b[nf][0], b[nf][1]);
        }
        __syncthreads();
    }

    // ---- epilogue ----
#pragma unroll
    for (int nf = 0; nf < NF; nf++) {
        int col = wn * (N2 / 4) + nf * 8 + tig * 2;
        float c0 = b2v[col], c1 = b2v[col + 1];
#pragma unroll
        for (int mf = 0; mf < 2; mf++) {
            int r0 = m0 + rA + mf * 16 + gid;
            float v0 = acc[mf][nf][0] + c0, v1 = acc[mf][nf][1] + c1;
            float v2 = acc[mf][nf][2] + c0, v3 = acc[mf][nf][3] + c1;
            if (OUTER_RELU) {
                v0 = fmaxf(v0, 0.f); v1 = fmaxf(v1, 0.f);
                v2 = fmaxf(v2, 0.f); v3 = fmaxf(v3, 0.f);
            }
            if (HALF_OUT) {
                __half* Ch = (__half*)Cv;
                if (r0 < M)
                    *(uint32_t*)&Ch[(size_t)r0 * N2 + col] = pack_h2(v0, v1);
                if (r0 + 8 < M)
                    *(uint32_t*)&Ch[(size_t)(r0 + 8) * N2 + col] = pack_h2(v2, v3);
            } else {
                float* Cf = (float*)Cv;
                if (r0 < M)
                    *(float2*)&Cf[(size_t)r0 * N2 + col] = make_float2(v0, v1);
                if (r0 + 8 < M)
                    *(float2*)&Cf[(size_t)(r0 + 8) * N2 + col] = make_float2(v2, v3);
            }
        }
    }
}

// ================= launch =================
extern "C" void kernel_launch(void* const* d_in, const int* in_sizes, int n_in,
                              void* d_out, int out_size)
{
    const float* x   = (const float*)d_in[0];
    const int*   ei  = (const int*)d_in[1];
    const float* W1a = (const float*)d_in[2];
    const float* b1a = (const float*)d_in[3];
    const float* W2a = (const float*)d_in[4];
    const float* b2a = (const float*)d_in[5];
    const float* W1b = (const float*)d_in[6];
    const float* b1b = (const float*)d_in[7];
    const float* W2b = (const float*)d_in[8];
    const float* b2b = (const float*)d_in[9];
    float* out = (float*)d_out;

    __half *xh, *agg1, *h, *agg2, *Wf1, *Wf2, *Wf3, *Wf4;
    int *cnt, *rowoff, *cursor, *csrsrc, *bsum;
    cudaGetSymbolAddress((void**)&xh,   g_xh);
    cudaGetSymbolAddress((void**)&agg1, g_agg1);
    cudaGetSymbolAddress((void**)&h,    g_h);
    cudaGetSymbolAddress((void**)&agg2, g_agg2);
    cudaGetSymbolAddress((void**)&Wf1,  g_Wf1);
    cudaGetSymbolAddress((void**)&Wf2,  g_Wf2);
    cudaGetSymbolAddress((void**)&Wf3,  g_Wf3);
    cudaGetSymbolAddress((void**)&Wf4,  g_Wf4);
    cudaGetSymbolAddress((void**)&cnt,    g_cnt);
    cudaGetSymbolAddress((void**)&rowoff, g_rowoff);
    cudaGetSymbolAddress((void**)&cursor, g_cursor);
    cudaGetSymbolAddress((void**)&csrsrc, g_csrsrc);
    cudaGetSymbolAddress((void**)&bsum,   g_bsum);

    const int* src = ei;
    const int* dst = ei + N_EDGES;

    const int mTiles = (N_NODES + 127) / 128;      // 782
    const int eBlocks = (N_EDGES + 255) / 256;
    const int nWarpBlocks = (N_NODES * 32 + 255) / 256;

    const int SM1 = (128 * 264 + 2 * 32 * HID_C) * 2;   // 100352 B
    const int SM2 = (128 * 264 + 2 * 32 * OUT_C) * 2;   //  83968 B
    cudaFuncSetAttribute(fused_mlp<IN_C,  HID_C, true,  true >,
                         cudaFuncAttributeMaxDynamicSharedMemorySize, SM1);
    cudaFuncSetAttribute(fused_mlp<HID_C, OUT_C, false, false>,
                         cudaFuncAttributeMaxDynamicSharedMemorySize, SM2);

    // ---- x -> fp16 ----
    {
        int n8 = N_NODES * IN_C / 8;   // 1.6M uint4s
        convert_kernel<<<(n8 + 255) / 256, 256>>>((const float4*)x, (uint4*)xh, n8);
    }

    // ---- CSR build (dst-sorted) ----
    cudaMemsetAsync(cnt, 0, N_NODES * sizeof(int));
    hist_kernel<<<eBlocks, 256>>>(dst, cnt);
    scan1_kernel<<<SCAN_NB, 1024>>>(cnt, rowoff, bsum);
    scan2_kernel<<<1, 128>>>(bsum);
    scan3_kernel<<<SCAN_NB, 1024>>>(rowoff, bsum, cursor);
    fill_kernel<<<eBlocks, 256>>>(src, dst, cursor, csrsrc);

    // ---- weight fragment packs (fp16) ----
    pack_kernel<IN_C,  HID_C><<<(IN_C * HID_C / 8 + 255) / 256, 256>>>(W1a, Wf1);
    pack_kernel<HID_C, HID_C><<<(HID_C * HID_C / 8 + 255) / 256, 256>>>(W2a, Wf2);
    pack_kernel<HID_C, HID_C><<<(HID_C * HID_C / 8 + 255) / 256, 256>>>(W1b, Wf3);
    pack_kernel<HID_C, OUT_C><<<(HID_C * OUT_C / 8 + 255) / 256, 256>>>(W2b, Wf4);

    // ---- conv1: reduce (fp16 x -> fp16 agg) + fused MLP (fp16 h out) ----
    csr_reduce_h16_128<<<nWarpBlocks, 256>>>(
        (const uint2*)xh, rowoff, csrsrc, agg1);
    fused_mlp<IN_C, HID_C, true, true><<<mTiles, 512, SM1>>>(
        agg1, Wf1, b1a, Wf2, b2a, h);

    // ---- conv2: reduce (fp16 h -> fp16 agg) + fused MLP (fp32 out) ----
    csr_reduce_h16_256<<<nWarpBlocks, 256>>>(
        (const uint4*)h, rowoff, csrsrc, agg2);
    fused_mlp<HID_C, OUT_C, false, false><<<mTiles, 512, SM2>>>(
        agg2, Wf3, b1b, Wf4, b2b, out);
}